// round 1
// baseline (speedup 1.0000x reference)
#include <cuda_runtime.h>
#include <math.h>

// Problem constants
#define NB 2
#define T  2048
#define D  1024
#define H  8
#define HD 128
#define M_TOT (NB * T)   // 4096

// Scratch for Q/K/V projections (16 MB each). Device globals: allocation-free.
__device__ float g_Q[M_TOT * D];
__device__ float g_K[M_TOT * D];
__device__ float g_V[M_TOT * D];

// ---------------------------------------------------------------------------
// GEMM (NT): C[m,n] = sum_k A[m,k] * W[n,k]
// A: [4096, 1024] row-major (k contiguous), W: [1024, 1024] row-major (k contiguous)
// 128x128 block tile, BK=16, 256 threads, 8x8 per-thread micro-tile.
// ---------------------------------------------------------------------------
__global__ __launch_bounds__(256, 2) void gemm_nt(const float* __restrict__ A,
                                                  const float* __restrict__ W,
                                                  float* __restrict__ C)
{
    __shared__ float As[16][128];
    __shared__ float Ws[16][128];

    const int tid = threadIdx.x;
    const int tx  = tid & 15;
    const int ty  = tid >> 4;
    const int mBase = blockIdx.y * 128;
    const int nBase = blockIdx.x * 128;

    float acc[8][8];
#pragma unroll
    for (int i = 0; i < 8; i++)
#pragma unroll
        for (int j = 0; j < 8; j++) acc[i][j] = 0.0f;

    for (int kt = 0; kt < D; kt += 16) {
        // Load 128x16 tiles of A and W, stored k-major in smem ([k][row])
#pragma unroll
        for (int p = 0; p < 2; p++) {
            int idx = tid + p * 256;      // 0..511
            int row = idx >> 2;           // 0..127
            int kq  = (idx & 3) << 2;     // 0,4,8,12
            float4 va = *(const float4*)(A + (size_t)(mBase + row) * D + kt + kq);
            As[kq + 0][row] = va.x;
            As[kq + 1][row] = va.y;
            As[kq + 2][row] = va.z;
            As[kq + 3][row] = va.w;
            float4 vw = *(const float4*)(W + (size_t)(nBase + row) * D + kt + kq);
            Ws[kq + 0][row] = vw.x;
            Ws[kq + 1][row] = vw.y;
            Ws[kq + 2][row] = vw.z;
            Ws[kq + 3][row] = vw.w;
        }
        __syncthreads();

#pragma unroll
        for (int kk = 0; kk < 16; kk++) {
            float a[8], b[8];
            *(float4*)&a[0] = *(const float4*)&As[kk][ty * 8];
            *(float4*)&a[4] = *(const float4*)&As[kk][ty * 8 + 4];
            *(float4*)&b[0] = *(const float4*)&Ws[kk][tx * 8];
            *(float4*)&b[4] = *(const float4*)&Ws[kk][tx * 8 + 4];
#pragma unroll
            for (int i = 0; i < 8; i++)
#pragma unroll
                for (int j = 0; j < 8; j++)
                    acc[i][j] = fmaf(a[i], b[j], acc[i][j]);
        }
        __syncthreads();
    }

#pragma unroll
    for (int i = 0; i < 8; i++) {
#pragma unroll
        for (int j = 0; j < 8; j += 4) {
            float4 o;
            o.x = acc[i][j + 0];
            o.y = acc[i][j + 1];
            o.z = acc[i][j + 2];
            o.w = acc[i][j + 3];
            *(float4*)(C + (size_t)(mBase + ty * 8 + i) * D + nBase + tx * 8 + j) = o;
        }
    }
}

// ---------------------------------------------------------------------------
// Fused attention (flash-style online softmax), fp32.
// One block = 64 query rows of one (batch, head). Loops over 32 key tiles of 64.
// 256 threads as (tx=16, ty=16). S-tile: thread owns 4x4 of 64x64.
// O accumulator: thread owns 4 rows x 8 cols of 64x128.
// Row stats (m, l) live in registers of threads 0..63.
// Dynamic smem layout (floats):
//   Qs[128][65]  k-major (transposed)   @ 0       (8320)
//   Ks[128][65]  k-major (transposed)   @ 8320    (8320)
//   Vs[64][128]  row-major              @ 16640   (8192)
//   Ps[64][65]   P tile (+col 64=alpha) @ 24832   (4160)
// Total 28992 floats = 115968 bytes
// ---------------------------------------------------------------------------
#define ATTN_SMEM_FLOATS 28992
#define ATTN_SMEM_BYTES  (ATTN_SMEM_FLOATS * 4)

__global__ __launch_bounds__(256, 2) void attn_kernel(const float* __restrict__ Q,
                                                      const float* __restrict__ K,
                                                      const float* __restrict__ V,
                                                      float* __restrict__ out)
{
    extern __shared__ float sm[];
    float* Qs = sm;                        // [128][65]
    float* Ks = sm + 128 * 65;             // [128][65]
    float* Vs = sm + 2 * 128 * 65;         // [64][128]
    float* Ps = sm + 2 * 128 * 65 + 64 * 128; // [64][65]

    const int tid = threadIdx.x;
    const int tx  = tid & 15;
    const int ty  = tid >> 4;
    const int bh  = blockIdx.y;   // b*H + h
    const int b   = bh >> 3;
    const int h   = bh & 7;
    const int t0  = blockIdx.x * 64;

    // Load Q tile once, transposed: Qs[k][row]
    const float* Qg = Q + (size_t)(b * T + t0) * D + h * HD;
#pragma unroll
    for (int p = 0; p < 8; p++) {
        int idx = tid + p * 256;    // 0..2047
        int row = idx >> 5;         // 0..63
        int kq  = (idx & 31) << 2;  // 0..124
        float4 v = *(const float4*)(Qg + (size_t)row * D + kq);
        Qs[(kq + 0) * 65 + row] = v.x;
        Qs[(kq + 1) * 65 + row] = v.y;
        Qs[(kq + 2) * 65 + row] = v.z;
        Qs[(kq + 3) * 65 + row] = v.w;
    }

    float acc[4][8];
#pragma unroll
    for (int i = 0; i < 4; i++)
#pragma unroll
        for (int j = 0; j < 8; j++) acc[i][j] = 0.0f;

    float m_r = -INFINITY;  // row stats (only meaningful for tid < 64)
    float l_r = 0.0f;

    for (int kt = 0; kt < T; kt += 64) {
        __syncthreads();  // previous iteration's readers of Ks/Vs/Ps done

        const float* Kg = K + (size_t)(b * T + kt) * D + h * HD;
        const float* Vg = V + (size_t)(b * T + kt) * D + h * HD;
#pragma unroll
        for (int p = 0; p < 8; p++) {
            int idx = tid + p * 256;
            int row = idx >> 5;
            int kq  = (idx & 31) << 2;
            float4 vk = *(const float4*)(Kg + (size_t)row * D + kq);
            Ks[(kq + 0) * 65 + row] = vk.x;
            Ks[(kq + 1) * 65 + row] = vk.y;
            Ks[(kq + 2) * 65 + row] = vk.z;
            Ks[(kq + 3) * 65 + row] = vk.w;
            float4 vv = *(const float4*)(Vg + (size_t)row * D + kq);
            *(float4*)(Vs + row * 128 + kq) = vv;
        }
        __syncthreads();

        // S = Q @ K^T (64x64), scaled by 1/sqrt(1024) = 1/32
        float s[4][4];
#pragma unroll
        for (int i = 0; i < 4; i++)
#pragma unroll
            for (int j = 0; j < 4; j++) s[i][j] = 0.0f;

#pragma unroll 8
        for (int k = 0; k < 128; k++) {
            float a[4], bb[4];
#pragma unroll
            for (int i = 0; i < 4; i++) a[i]  = Qs[k * 65 + ty * 4 + i];
#pragma unroll
            for (int j = 0; j < 4; j++) bb[j] = Ks[k * 65 + tx * 4 + j];
#pragma unroll
            for (int i = 0; i < 4; i++)
#pragma unroll
                for (int j = 0; j < 4; j++)
                    s[i][j] = fmaf(a[i], bb[j], s[i][j]);
        }
#pragma unroll
        for (int i = 0; i < 4; i++)
#pragma unroll
            for (int j = 0; j < 4; j++)
                Ps[(ty * 4 + i) * 65 + tx * 4 + j] = s[i][j] * 0.03125f;
        __syncthreads();

        // Online softmax row update (threads 0..63, one row each)
        if (tid < 64) {
            const int r = tid;
            float mx = m_r;
#pragma unroll 8
            for (int c = 0; c < 64; c++) mx = fmaxf(mx, Ps[r * 65 + c]);
            float alpha = __expf(m_r - mx);   // 0 on first tile (m_r = -inf)
            float ssum = 0.0f;
#pragma unroll 8
            for (int c = 0; c < 64; c++) {
                float pv = __expf(Ps[r * 65 + c] - mx);
                Ps[r * 65 + c] = pv;
                ssum += pv;
            }
            l_r = l_r * alpha + ssum;
            m_r = mx;
            Ps[r * 65 + 64] = alpha;
        }
        __syncthreads();

        // acc = acc * alpha + P @ V
#pragma unroll
        for (int i = 0; i < 4; i++) {
            float alpha = Ps[(ty * 4 + i) * 65 + 64];
#pragma unroll
            for (int j = 0; j < 8; j++) acc[i][j] *= alpha;
        }
#pragma unroll 4
        for (int k = 0; k < 64; k++) {
            float pv[4];
#pragma unroll
            for (int i = 0; i < 4; i++) pv[i] = Ps[(ty * 4 + i) * 65 + k];
            float vv[8];
            *(float4*)&vv[0] = *(const float4*)(Vs + k * 128 + tx * 8);
            *(float4*)&vv[4] = *(const float4*)(Vs + k * 128 + tx * 8 + 4);
#pragma unroll
            for (int i = 0; i < 4; i++)
#pragma unroll
                for (int j = 0; j < 8; j++)
                    acc[i][j] = fmaf(pv[i], vv[j], acc[i][j]);
        }
    }

    // Publish final l to smem, then normalize and write out
    __syncthreads();
    if (tid < 64) Ps[tid * 65 + 64] = l_r;
    __syncthreads();

#pragma unroll
    for (int i = 0; i < 4; i++) {
        float inv = 1.0f / Ps[(ty * 4 + i) * 65 + 64];
        size_t base = (size_t)(b * T + t0 + ty * 4 + i) * D + h * HD + tx * 8;
#pragma unroll
        for (int j = 0; j < 8; j += 4) {
            float4 o;
            o.x = acc[i][j + 0] * inv;
            o.y = acc[i][j + 1] * inv;
            o.z = acc[i][j + 2] * inv;
            o.w = acc[i][j + 3] * inv;
            *(float4*)(out + base + j) = o;
        }
    }
}

// ---------------------------------------------------------------------------
// Launch
// ---------------------------------------------------------------------------
extern "C" void kernel_launch(void* const* d_in, const int* in_sizes, int n_in,
                              void* d_out, int out_size)
{
    const float* query = (const float*)d_in[0];  // [2,2048,1024]
    const float* keys  = (const float*)d_in[1];  // [2,2048,1024]
    const float* Wq    = (const float*)d_in[2];  // [1024,1024]
    const float* Wk    = (const float*)d_in[3];
    const float* Wv    = (const float*)d_in[4];
    float* out = (float*)d_out;                  // [2,2048,1024]

    float *qp, *kp, *vp;
    cudaGetSymbolAddress((void**)&qp, g_Q);
    cudaGetSymbolAddress((void**)&kp, g_K);
    cudaGetSymbolAddress((void**)&vp, g_V);

    dim3 gg(D / 128, M_TOT / 128);  // (8, 32)
    gemm_nt<<<gg, 256>>>(query, Wq, qp);
    gemm_nt<<<gg, 256>>>(keys,  Wk, kp);
    gemm_nt<<<gg, 256>>>(keys,  Wv, vp);

    cudaFuncSetAttribute(attn_kernel,
                         cudaFuncAttributeMaxDynamicSharedMemorySize,
                         ATTN_SMEM_BYTES);
    dim3 ga(T / 64, NB * H);  // (32, 16)
    attn_kernel<<<ga, 256, ATTN_SMEM_BYTES>>>(qp, kp, vp, out);
}

// round 3
// speedup vs baseline: 3.4642x; 3.4642x over previous
#include <cuda_runtime.h>
#include <cuda_bf16.h>
#include <stdint.h>

// ===========================================================================
// Problem constants
// ===========================================================================
#define TOK   4096      // 2*2048 tokens
#define DIM   1024
#define TSEQ  2048
#define NBH   16        // batch*heads
#define SCALE 0.03125f  // 1/sqrt(1024)

// ===========================================================================
// Device scratch (allocation-free: __device__ globals)
// ===========================================================================
__device__ __align__(16) __nv_bfloat16 g_qh[TOK * DIM], g_ql[TOK * DIM];
__device__ __align__(16) __nv_bfloat16 g_kh[TOK * DIM], g_kl[TOK * DIM];
__device__ __align__(16) __nv_bfloat16 g_Wqh[DIM * DIM], g_Wql[DIM * DIM];
__device__ __align__(16) __nv_bfloat16 g_Wkh[DIM * DIM], g_Wkl[DIM * DIM];
__device__ __align__(16) __nv_bfloat16 g_Wvh[DIM * DIM], g_Wvl[DIM * DIM];
__device__ __align__(16) __nv_bfloat16 g_Qh[TOK * DIM], g_Ql[TOK * DIM];
__device__ __align__(16) __nv_bfloat16 g_Kh[TOK * DIM], g_Kl[TOK * DIM];
__device__ __align__(16) __nv_bfloat16 g_Vth[DIM * TOK], g_Vtl[DIM * TOK]; // V^T
__device__ __align__(16) float         g_S[(size_t)NBH * TSEQ * TSEQ];
__device__ __align__(16) __nv_bfloat16 g_Ph[(size_t)NBH * TSEQ * TSEQ];
__device__ __align__(16) __nv_bfloat16 g_Pl[(size_t)NBH * TSEQ * TSEQ];

// ===========================================================================
// Helpers
// ===========================================================================
__device__ __forceinline__ uint32_t smem_u32(const void* p) {
    uint32_t a;
    asm("{ .reg .u64 t; cvta.to.shared.u64 t, %1; cvt.u32.u64 %0, t; }" : "=r"(a) : "l"(p));
    return a;
}
#define SWZ128(off) ((off) ^ (((off) >> 3) & 0x70))

#define LDSM4(r0, r1, r2, r3, addr) \
    asm volatile("ldmatrix.sync.aligned.m8n8.x4.shared.b16 {%0,%1,%2,%3}, [%4];" \
                 : "=r"(r0), "=r"(r1), "=r"(r2), "=r"(r3) : "r"(addr))

#define MMA16816(d, a, b0, b1) \
    asm volatile("mma.sync.aligned.m16n8k16.row.col.f32.bf16.bf16.f32 " \
                 "{%0,%1,%2,%3}, {%4,%5,%6,%7}, {%8,%9}, {%0,%1,%2,%3};" \
                 : "+f"((d)[0]), "+f"((d)[1]), "+f"((d)[2]), "+f"((d)[3]) \
                 : "r"((a)[0]), "r"((a)[1]), "r"((a)[2]), "r"((a)[3]), \
                   "r"(b0), "r"(b1))

#define CP_ASYNC16(dst, src) \
    asm volatile("cp.async.cg.shared.global [%0], [%1], 16;" :: "r"(dst), "l"(src))
#define CP_COMMIT()  asm volatile("cp.async.commit_group;" ::: "memory")
#define CP_WAIT0()   asm volatile("cp.async.wait_group 0;" ::: "memory")
#define CP_WAIT1()   asm volatile("cp.async.wait_group 1;" ::: "memory")

// ===========================================================================
// Generic batched NT GEMM, bf16 hi/lo 3-MMA split, mma.sync tensor path.
// C[m,n] = sum_k A[m,k]*B[n,k]. grid (N/128, M/128, batch); block 256.
// z -> zb = z>>3, zh = z&7.
// mode: 0 = fp32 store, 1 = split bf16 store, 2 = transposed split store
// Smem: 2 stages x (Ah,Al,Bh,Bl 16KB each) = 131072 B
// ===========================================================================
#define G_STAGE      65536
#define G_SMEM_TOTAL (2 * G_STAGE)

__device__ __forceinline__ void cpa_tile(const __nv_bfloat16* __restrict__ src,
                                         int rowBase, int ld, int kt,
                                         uint32_t dstBase, int tid) {
#pragma unroll
    for (int i = 0; i < 4; i++) {
        int u = tid + i * 256;          // 0..1023
        int r = u >> 3;                 // row 0..127
        int cb = (u & 7) << 4;          // byte col 0..112
        uint32_t dst = dstBase + SWZ128((r << 7) | cb);
        const void* gsrc = src + (size_t)(rowBase + r) * ld + kt + ((u & 7) << 3);
        CP_ASYNC16(dst, gsrc);
    }
}

__global__ __launch_bounds__(256, 1) void gemm_bf16x3(
    const __nv_bfloat16* __restrict__ Ah, const __nv_bfloat16* __restrict__ Al,
    int lda, long long sAb, long long sAh,
    const __nv_bfloat16* __restrict__ Bh, const __nv_bfloat16* __restrict__ Bl,
    int ldb, long long sBb, long long sBh,
    float* Cf, __nv_bfloat16* Ch, __nv_bfloat16* Cl,
    int ldc, long long sCb, long long sCh,
    int K, int mode)
{
    extern __shared__ char smem[];
    const uint32_t sb = smem_u32(smem);
    const int tid  = threadIdx.x;
    const int wid  = tid >> 5;
    const int lane = tid & 31;
    const int wm   = wid & 3;          // 4 warps along M
    const int wn   = wid >> 2;         // 2 warps along N
    const int nBase = blockIdx.x * 128;
    const int mBase = blockIdx.y * 128;
    const int z = blockIdx.z, zb = z >> 3, zh = z & 7;

    const __nv_bfloat16* Ahp = Ah + (size_t)zb * sAb + (size_t)zh * sAh;
    const __nv_bfloat16* Alp = Al + (size_t)zb * sAb + (size_t)zh * sAh;
    const __nv_bfloat16* Bhp = Bh + (size_t)zb * sBb + (size_t)zh * sBh;
    const __nv_bfloat16* Blp = Bl + (size_t)zb * sBb + (size_t)zh * sBh;
    const size_t offC = (size_t)zb * sCb + (size_t)zh * sCh;

    const int nc = K >> 6;

    // prologue: stage 0
    cpa_tile(Ahp, mBase, lda, 0, sb,         tid);
    cpa_tile(Alp, mBase, lda, 0, sb + 16384, tid);
    cpa_tile(Bhp, nBase, ldb, 0, sb + 32768, tid);
    cpa_tile(Blp, nBase, ldb, 0, sb + 49152, tid);
    CP_COMMIT();

    float acc[2][8][4];
#pragma unroll
    for (int i = 0; i < 2; i++)
#pragma unroll
        for (int j = 0; j < 8; j++)
#pragma unroll
            for (int q = 0; q < 4; q++) acc[i][j][q] = 0.0f;

    // per-lane ldmatrix address components (byte offsets within a tile)
    // A frag: r = wm*32 + mi*16 + ((lane>>3)&1)*8 + (lane&7), kb = kk*32 + (lane>>4)*16
    const int arow = wm * 32 + ((lane >> 3) & 1) * 8 + (lane & 7);
    const int akb  = (lane >> 4) << 4;
    // B frag: n = wn*64 + nn*16 + (lane>>4)*8 + (lane&7), kb = kk*32 + ((lane>>3)&1)*16
    const int brow = wn * 64 + ((lane >> 4) << 3) + (lane & 7);
    const int bkb  = ((lane >> 3) & 1) << 4;

    for (int c = 0; c < nc; c++) {
        const int s = c & 1;
        if (c + 1 < nc) {
            const uint32_t st = sb + (s ^ 1) * G_STAGE;
            const int kt = (c + 1) << 6;
            cpa_tile(Ahp, mBase, lda, kt, st,         tid);
            cpa_tile(Alp, mBase, lda, kt, st + 16384, tid);
            cpa_tile(Bhp, nBase, ldb, kt, st + 32768, tid);
            cpa_tile(Blp, nBase, ldb, kt, st + 49152, tid);
            CP_COMMIT();
            CP_WAIT1();
        } else {
            CP_WAIT0();
        }
        __syncthreads();

        const uint32_t Ahb = sb + s * G_STAGE;
        const uint32_t Alb = Ahb + 16384;
        const uint32_t Bhb = Ahb + 32768;
        const uint32_t Blb = Ahb + 49152;

#pragma unroll
        for (int kk = 0; kk < 4; kk++) {
            const int kb = kk * 32;
            uint32_t ah[2][4], al[2][4];
#pragma unroll
            for (int mi = 0; mi < 2; mi++) {
                const int r = arow + mi * 16;
                const uint32_t off = SWZ128((r << 7) | (kb + akb));
                LDSM4(ah[mi][0], ah[mi][1], ah[mi][2], ah[mi][3], Ahb + off);
                LDSM4(al[mi][0], al[mi][1], al[mi][2], al[mi][3], Alb + off);
            }
#pragma unroll
            for (int nn = 0; nn < 4; nn++) {
                const int n = brow + nn * 16;
                const uint32_t off = SWZ128((n << 7) | (kb + bkb));
                uint32_t bh0, bh1, bh2, bh3, bl0, bl1, bl2, bl3;
                LDSM4(bh0, bh1, bh2, bh3, Bhb + off);
                LDSM4(bl0, bl1, bl2, bl3, Blb + off);
#pragma unroll
                for (int mi = 0; mi < 2; mi++) {
                    MMA16816(acc[mi][nn * 2],     ah[mi], bh0, bh1);
                    MMA16816(acc[mi][nn * 2],     al[mi], bh0, bh1);
                    MMA16816(acc[mi][nn * 2],     ah[mi], bl0, bl1);
                    MMA16816(acc[mi][nn * 2 + 1], ah[mi], bh2, bh3);
                    MMA16816(acc[mi][nn * 2 + 1], al[mi], bh2, bh3);
                    MMA16816(acc[mi][nn * 2 + 1], ah[mi], bl2, bl3);
                }
            }
        }
        __syncthreads();
    }

    // epilogue
    const int erow = mBase + wm * 32 + (lane >> 2);      // +mi*16, +8 for upper
    const int ecol = nBase + wn * 64 + 2 * (lane & 3);   // +ni*8

    if (mode == 0) {
#pragma unroll
        for (int mi = 0; mi < 2; mi++)
#pragma unroll
            for (int ni = 0; ni < 8; ni++) {
                const float* a = acc[mi][ni];
                float* d0 = Cf + offC + (size_t)(erow + mi * 16) * ldc + ecol + ni * 8;
                float* d1 = d0 + 8 * ldc;
                *reinterpret_cast<float2*>(d0) = make_float2(a[0], a[1]);
                *reinterpret_cast<float2*>(d1) = make_float2(a[2], a[3]);
            }
    } else if (mode == 1) {
#pragma unroll
        for (int mi = 0; mi < 2; mi++)
#pragma unroll
            for (int ni = 0; ni < 8; ni++) {
                const float* a = acc[mi][ni];
#pragma unroll
                for (int half = 0; half < 2; half++) {
                    float v0 = a[half * 2], v1 = a[half * 2 + 1];
                    __nv_bfloat16 h0 = __float2bfloat16(v0);
                    __nv_bfloat16 h1 = __float2bfloat16(v1);
                    __nv_bfloat16 l0 = __float2bfloat16(v0 - __bfloat162float(h0));
                    __nv_bfloat16 l1 = __float2bfloat16(v1 - __bfloat162float(h1));
                    size_t o = offC + (size_t)(erow + mi * 16 + half * 8) * ldc + ecol + ni * 8;
                    __nv_bfloat162 hp; hp.x = h0; hp.y = h1;
                    __nv_bfloat162 lp; lp.x = l0; lp.y = l1;
                    *reinterpret_cast<__nv_bfloat162*>(Ch + o) = hp;
                    *reinterpret_cast<__nv_bfloat162*>(Cl + o) = lp;
                }
            }
    } else {
        // transposed split: C^T[n][m]
#pragma unroll
        for (int mi = 0; mi < 2; mi++)
#pragma unroll
            for (int ni = 0; ni < 8; ni++) {
                const float* a = acc[mi][ni];
#pragma unroll
                for (int q = 0; q < 4; q++) {
                    float v = a[q];
                    int row = erow + mi * 16 + (q >> 1) * 8;
                    int col = ecol + ni * 8 + (q & 1);
                    __nv_bfloat16 h = __float2bfloat16(v);
                    __nv_bfloat16 l = __float2bfloat16(v - __bfloat162float(h));
                    size_t o = offC + (size_t)col * ldc + row;
                    Ch[o] = h;
                    Cl[o] = l;
                }
            }
    }
}

// ===========================================================================
// fp32 -> bf16 hi/lo split
// ===========================================================================
__global__ __launch_bounds__(256) void split_kernel(const float* __restrict__ in,
                                                    __nv_bfloat16* __restrict__ hi,
                                                    __nv_bfloat16* __restrict__ lo,
                                                    int n4)
{
    int i = blockIdx.x * 256 + threadIdx.x;
    if (i >= n4) return;
    float4 v = reinterpret_cast<const float4*>(in)[i];
    float vv[4] = {v.x, v.y, v.z, v.w};
    union { __nv_bfloat16 b[4]; uint2 u; } hb, lb;
#pragma unroll
    for (int j = 0; j < 4; j++) {
        __nv_bfloat16 h = __float2bfloat16(vv[j]);
        hb.b[j] = h;
        lb.b[j] = __float2bfloat16(vv[j] - __bfloat162float(h));
    }
    reinterpret_cast<uint2*>(hi)[i] = hb.u;
    reinterpret_cast<uint2*>(lo)[i] = lb.u;
}

// ===========================================================================
// Row softmax: one warp per 2048-length row, fp32, P stored as bf16 hi/lo
// ===========================================================================
__global__ __launch_bounds__(256) void softmax_kernel(const float* __restrict__ S,
                                                      __nv_bfloat16* __restrict__ Ph,
                                                      __nv_bfloat16* __restrict__ Pl)
{
    const int warp = threadIdx.x >> 5, lane = threadIdx.x & 31;
    const size_t row = (size_t)blockIdx.x * 8 + warp;
    const float4* src = reinterpret_cast<const float4*>(S + row * TSEQ);

    float4 v[16];
    float mx = -1e30f;
#pragma unroll
    for (int i = 0; i < 16; i++) {
        float4 t = src[lane + i * 32];
        t.x *= SCALE; t.y *= SCALE; t.z *= SCALE; t.w *= SCALE;
        v[i] = t;
        mx = fmaxf(mx, fmaxf(fmaxf(t.x, t.y), fmaxf(t.z, t.w)));
    }
#pragma unroll
    for (int o = 16; o > 0; o >>= 1) mx = fmaxf(mx, __shfl_xor_sync(0xffffffffu, mx, o));

    float sum = 0.0f;
#pragma unroll
    for (int i = 0; i < 16; i++) {
        v[i].x = __expf(v[i].x - mx);
        v[i].y = __expf(v[i].y - mx);
        v[i].z = __expf(v[i].z - mx);
        v[i].w = __expf(v[i].w - mx);
        sum += v[i].x + v[i].y + v[i].z + v[i].w;
    }
#pragma unroll
    for (int o = 16; o > 0; o >>= 1) sum += __shfl_xor_sync(0xffffffffu, sum, o);
    const float inv = 1.0f / sum;

    uint2* dh = reinterpret_cast<uint2*>(Ph + row * TSEQ);
    uint2* dl = reinterpret_cast<uint2*>(Pl + row * TSEQ);
#pragma unroll
    for (int i = 0; i < 16; i++) {
        float p[4] = {v[i].x * inv, v[i].y * inv, v[i].z * inv, v[i].w * inv};
        union { __nv_bfloat16 b[4]; uint2 u; } hb, lb;
#pragma unroll
        for (int j = 0; j < 4; j++) {
            __nv_bfloat16 h = __float2bfloat16(p[j]);
            hb.b[j] = h;
            lb.b[j] = __float2bfloat16(p[j] - __bfloat162float(h));
        }
        dh[lane + i * 32] = hb.u;
        dl[lane + i * 32] = lb.u;
    }
}

// ===========================================================================
// Launch
// ===========================================================================
extern "C" void kernel_launch(void* const* d_in, const int* in_sizes, int n_in,
                              void* d_out, int out_size)
{
    const float* query = (const float*)d_in[0];
    const float* keys  = (const float*)d_in[1];
    const float* Wq    = (const float*)d_in[2];
    const float* Wk    = (const float*)d_in[3];
    const float* Wv    = (const float*)d_in[4];
    float* out = (float*)d_out;

    __nv_bfloat16 *qh, *ql, *kh, *kl, *Wqh, *Wql, *Wkh, *Wkl, *Wvh, *Wvl;
    __nv_bfloat16 *Qh, *Ql, *Kh, *Kl, *Vth, *Vtl, *Ph, *Pl;
    float* Sp;
    cudaGetSymbolAddress((void**)&qh, g_qh);   cudaGetSymbolAddress((void**)&ql, g_ql);
    cudaGetSymbolAddress((void**)&kh, g_kh);   cudaGetSymbolAddress((void**)&kl, g_kl);
    cudaGetSymbolAddress((void**)&Wqh, g_Wqh); cudaGetSymbolAddress((void**)&Wql, g_Wql);
    cudaGetSymbolAddress((void**)&Wkh, g_Wkh); cudaGetSymbolAddress((void**)&Wkl, g_Wkl);
    cudaGetSymbolAddress((void**)&Wvh, g_Wvh); cudaGetSymbolAddress((void**)&Wvl, g_Wvl);
    cudaGetSymbolAddress((void**)&Qh, g_Qh);   cudaGetSymbolAddress((void**)&Ql, g_Ql);
    cudaGetSymbolAddress((void**)&Kh, g_Kh);   cudaGetSymbolAddress((void**)&Kl, g_Kl);
    cudaGetSymbolAddress((void**)&Vth, g_Vth); cudaGetSymbolAddress((void**)&Vtl, g_Vtl);
    cudaGetSymbolAddress((void**)&Sp, g_S);
    cudaGetSymbolAddress((void**)&Ph, g_Ph);   cudaGetSymbolAddress((void**)&Pl, g_Pl);

    cudaFuncSetAttribute(gemm_bf16x3, cudaFuncAttributeMaxDynamicSharedMemorySize,
                         G_SMEM_TOTAL);

    // 1) split fp32 inputs into bf16 hi/lo
    split_kernel<<<(TOK * DIM / 4 + 255) / 256, 256>>>(query, qh, ql, TOK * DIM / 4);
    split_kernel<<<(TOK * DIM / 4 + 255) / 256, 256>>>(keys,  kh, kl, TOK * DIM / 4);
    split_kernel<<<(DIM * DIM / 4 + 255) / 256, 256>>>(Wq, Wqh, Wql, DIM * DIM / 4);
    split_kernel<<<(DIM * DIM / 4 + 255) / 256, 256>>>(Wk, Wkh, Wkl, DIM * DIM / 4);
    split_kernel<<<(DIM * DIM / 4 + 255) / 256, 256>>>(Wv, Wvh, Wvl, DIM * DIM / 4);

    // 2) projections
    dim3 gp(DIM / 128, TOK / 128, 1);
    gemm_bf16x3<<<gp, 256, G_SMEM_TOTAL>>>(qh, ql, DIM, 0, 0, Wqh, Wql, DIM, 0, 0,
                                           nullptr, Qh, Ql, DIM, 0, 0, DIM, 1);
    gemm_bf16x3<<<gp, 256, G_SMEM_TOTAL>>>(kh, kl, DIM, 0, 0, Wkh, Wkl, DIM, 0, 0,
                                           nullptr, Kh, Kl, DIM, 0, 0, DIM, 1);
    // V projection stored transposed: Vt[unit][token]
    gemm_bf16x3<<<gp, 256, G_SMEM_TOTAL>>>(kh, kl, DIM, 0, 0, Wvh, Wvl, DIM, 0, 0,
                                           nullptr, Vth, Vtl, TOK, 0, 0, DIM, 2);

    // 3) S[z,q,k] = Q[b,q,h,:] . K[b,k,h,:]  (K = head_dim = 128)
    dim3 gs(TSEQ / 128, TSEQ / 128, NBH);
    gemm_bf16x3<<<gs, 256, G_SMEM_TOTAL>>>(
        Qh, Ql, DIM, (long long)TSEQ * DIM, 128,
        Kh, Kl, DIM, (long long)TSEQ * DIM, 128,
        Sp, nullptr, nullptr, TSEQ,
        8LL * TSEQ * TSEQ, (long long)TSEQ * TSEQ, 128, 0);

    // 4) softmax rows -> P (split bf16)
    softmax_kernel<<<(NBH * TSEQ) / 8, 256>>>(Sp, Ph, Pl);

    // 5) out[b,q,h*128+d] = sum_k P[z,q,k] * Vt[h*128+d, b*2048+k]
    dim3 gv(1, TSEQ / 128, NBH);
    gemm_bf16x3<<<gv, 256, G_SMEM_TOTAL>>>(
        Ph, Pl, TSEQ, 8LL * TSEQ * TSEQ, (long long)TSEQ * TSEQ,
        Vth, Vtl, TOK, TSEQ, 128LL * TOK,
        out, nullptr, nullptr, DIM,
        (long long)TSEQ * DIM, 128, TSEQ, 0);
}

// round 4
// speedup vs baseline: 4.1939x; 1.2106x over previous
#include <cuda_runtime.h>
#include <cuda_bf16.h>
#include <stdint.h>

// ===========================================================================
// Problem constants
// ===========================================================================
#define TOK   4096      // 2*2048 tokens
#define DIM   1024
#define TSEQ  2048
#define NBH   16
#define QSCALE 0.03125f // 1/sqrt(1024) = 2^-5, exact in bf16

// ===========================================================================
// Device scratch (allocation-free)
// ===========================================================================
__device__ __align__(16) __nv_bfloat16 g_qh[TOK * DIM], g_ql[TOK * DIM];
__device__ __align__(16) __nv_bfloat16 g_kh[TOK * DIM], g_kl[TOK * DIM];
__device__ __align__(16) __nv_bfloat16 g_Wqh[DIM * DIM], g_Wql[DIM * DIM];
__device__ __align__(16) __nv_bfloat16 g_Wkh[DIM * DIM], g_Wkl[DIM * DIM];
__device__ __align__(16) __nv_bfloat16 g_Wvh[DIM * DIM], g_Wvl[DIM * DIM];
__device__ __align__(16) __nv_bfloat16 g_Qh[TOK * DIM], g_Ql[TOK * DIM];   // prescaled by 2^-5
__device__ __align__(16) __nv_bfloat16 g_Kh[TOK * DIM], g_Kl[TOK * DIM];
__device__ __align__(16) __nv_bfloat16 g_Vth[DIM * TOK], g_Vtl[DIM * TOK]; // V^T

// ===========================================================================
// Helpers
// ===========================================================================
__device__ __forceinline__ uint32_t smem_u32(const void* p) {
    uint32_t a;
    asm("{ .reg .u64 t; cvta.to.shared.u64 t, %1; cvt.u32.u64 %0, t; }" : "=r"(a) : "l"(p));
    return a;
}
#define SWZ128(off) ((off) ^ (((off) >> 3) & 0x70))

#define LDSM4(r0, r1, r2, r3, addr) \
    asm volatile("ldmatrix.sync.aligned.m8n8.x4.shared.b16 {%0,%1,%2,%3}, [%4];" \
                 : "=r"(r0), "=r"(r1), "=r"(r2), "=r"(r3) : "r"(addr))

#define MMA16816(d, a, b0, b1) \
    asm volatile("mma.sync.aligned.m16n8k16.row.col.f32.bf16.bf16.f32 " \
                 "{%0,%1,%2,%3}, {%4,%5,%6,%7}, {%8,%9}, {%0,%1,%2,%3};" \
                 : "+f"((d)[0]), "+f"((d)[1]), "+f"((d)[2]), "+f"((d)[3]) \
                 : "r"((a)[0]), "r"((a)[1]), "r"((a)[2]), "r"((a)[3]), \
                   "r"(b0), "r"(b1))

#define CP_ASYNC16(dst, src) \
    asm volatile("cp.async.cg.shared.global [%0], [%1], 16;" :: "r"(dst), "l"(src))
#define CP_COMMIT()  asm volatile("cp.async.commit_group;" ::: "memory")
#define CP_WAIT0()   asm volatile("cp.async.wait_group 0;" ::: "memory")
#define CP_WAIT1()   asm volatile("cp.async.wait_group 1;" ::: "memory")

__device__ __forceinline__ void split2(float v0, float v1, uint32_t& hi, uint32_t& lo) {
    __nv_bfloat16 h0 = __float2bfloat16(v0), h1 = __float2bfloat16(v1);
    __nv_bfloat16 l0 = __float2bfloat16(v0 - __bfloat162float(h0));
    __nv_bfloat16 l1 = __float2bfloat16(v1 - __bfloat162float(h1));
    __nv_bfloat162 hp; hp.x = h0; hp.y = h1;
    __nv_bfloat162 lp; lp.x = l0; lp.y = l1;
    hi = *reinterpret_cast<uint32_t*>(&hp);
    lo = *reinterpret_cast<uint32_t*>(&lp);
}

// ===========================================================================
// Projection GEMM (NT): C[m,n] = sum_k A[m,k]*B[n,k], bf16 hi/lo 3-MMA split.
// grid (N/128, M/128); block 256; lda = ldb = DIM; K = DIM.
// mode 1: split bf16 store (scaled); mode 2: transposed split store (scaled)
// ===========================================================================
#define G_STAGE      65536
#define G_SMEM_TOTAL (2 * G_STAGE)

__device__ __forceinline__ void cpa_tile(const __nv_bfloat16* __restrict__ src,
                                         int rowBase, int kt,
                                         uint32_t dstBase, int tid) {
#pragma unroll
    for (int i = 0; i < 4; i++) {
        int u = tid + i * 256;
        int r = u >> 3;
        int cb = (u & 7) << 4;
        uint32_t dst = dstBase + SWZ128((r << 7) | cb);
        const void* gsrc = src + (size_t)(rowBase + r) * DIM + kt + ((u & 7) << 3);
        CP_ASYNC16(dst, gsrc);
    }
}

__global__ __launch_bounds__(256, 1) void gemm_proj(
    const __nv_bfloat16* __restrict__ Ah, const __nv_bfloat16* __restrict__ Al,
    const __nv_bfloat16* __restrict__ Bh, const __nv_bfloat16* __restrict__ Bl,
    __nv_bfloat16* Ch, __nv_bfloat16* Cl, int ldc, int mode, float cscale)
{
    extern __shared__ char smem[];
    const uint32_t sb = smem_u32(smem);
    const int tid  = threadIdx.x;
    const int wid  = tid >> 5;
    const int lane = tid & 31;
    const int wm   = wid & 3;
    const int wn   = wid >> 2;
    const int nBase = blockIdx.x * 128;
    const int mBase = blockIdx.y * 128;

    const int nc = DIM >> 6;

    cpa_tile(Ah, mBase, 0, sb,         tid);
    cpa_tile(Al, mBase, 0, sb + 16384, tid);
    cpa_tile(Bh, nBase, 0, sb + 32768, tid);
    cpa_tile(Bl, nBase, 0, sb + 49152, tid);
    CP_COMMIT();

    float acc[2][8][4];
#pragma unroll
    for (int i = 0; i < 2; i++)
#pragma unroll
        for (int j = 0; j < 8; j++)
#pragma unroll
            for (int q = 0; q < 4; q++) acc[i][j][q] = 0.0f;

    const int arow = wm * 32 + ((lane >> 3) & 1) * 8 + (lane & 7);
    const int akb  = (lane >> 4) << 4;
    const int brow = wn * 64 + ((lane >> 4) << 3) + (lane & 7);
    const int bkb  = ((lane >> 3) & 1) << 4;

    for (int c = 0; c < nc; c++) {
        const int s = c & 1;
        if (c + 1 < nc) {
            const uint32_t st = sb + (s ^ 1) * G_STAGE;
            const int kt = (c + 1) << 6;
            cpa_tile(Ah, mBase, kt, st,         tid);
            cpa_tile(Al, mBase, kt, st + 16384, tid);
            cpa_tile(Bh, nBase, kt, st + 32768, tid);
            cpa_tile(Bl, nBase, kt, st + 49152, tid);
            CP_COMMIT();
            CP_WAIT1();
        } else {
            CP_WAIT0();
        }
        __syncthreads();

        const uint32_t Ahb = sb + s * G_STAGE;
        const uint32_t Alb = Ahb + 16384;
        const uint32_t Bhb = Ahb + 32768;
        const uint32_t Blb = Ahb + 49152;

#pragma unroll
        for (int kk = 0; kk < 4; kk++) {
            const int kb = kk * 32;
            uint32_t ah[2][4], al[2][4];
#pragma unroll
            for (int mi = 0; mi < 2; mi++) {
                const int r = arow + mi * 16;
                const uint32_t off = SWZ128((r << 7) | (kb + akb));
                LDSM4(ah[mi][0], ah[mi][1], ah[mi][2], ah[mi][3], Ahb + off);
                LDSM4(al[mi][0], al[mi][1], al[mi][2], al[mi][3], Alb + off);
            }
#pragma unroll
            for (int nn = 0; nn < 4; nn++) {
                const int n = brow + nn * 16;
                const uint32_t off = SWZ128((n << 7) | (kb + bkb));
                uint32_t bh0, bh1, bh2, bh3, bl0, bl1, bl2, bl3;
                LDSM4(bh0, bh1, bh2, bh3, Bhb + off);
                LDSM4(bl0, bl1, bl2, bl3, Blb + off);
#pragma unroll
                for (int mi = 0; mi < 2; mi++) {
                    MMA16816(acc[mi][nn * 2],     ah[mi], bh0, bh1);
                    MMA16816(acc[mi][nn * 2],     al[mi], bh0, bh1);
                    MMA16816(acc[mi][nn * 2],     ah[mi], bl0, bl1);
                    MMA16816(acc[mi][nn * 2 + 1], ah[mi], bh2, bh3);
                    MMA16816(acc[mi][nn * 2 + 1], al[mi], bh2, bh3);
                    MMA16816(acc[mi][nn * 2 + 1], ah[mi], bl2, bl3);
                }
            }
        }
        __syncthreads();
    }

    const int erow = mBase + wm * 32 + (lane >> 2);
    const int ecol = nBase + wn * 64 + 2 * (lane & 3);

    if (mode == 1) {
#pragma unroll
        for (int mi = 0; mi < 2; mi++)
#pragma unroll
            for (int ni = 0; ni < 8; ni++) {
                const float* a = acc[mi][ni];
#pragma unroll
                for (int half = 0; half < 2; half++) {
                    uint32_t hp, lp;
                    split2(a[half * 2] * cscale, a[half * 2 + 1] * cscale, hp, lp);
                    size_t o = (size_t)(erow + mi * 16 + half * 8) * ldc + ecol + ni * 8;
                    *reinterpret_cast<uint32_t*>(Ch + o) = hp;
                    *reinterpret_cast<uint32_t*>(Cl + o) = lp;
                }
            }
    } else {
#pragma unroll
        for (int mi = 0; mi < 2; mi++)
#pragma unroll
            for (int ni = 0; ni < 8; ni++) {
                const float* a = acc[mi][ni];
#pragma unroll
                for (int q = 0; q < 4; q++) {
                    float v = a[q] * cscale;
                    int row = erow + mi * 16 + (q >> 1) * 8;
                    int col = ecol + ni * 8 + (q & 1);
                    __nv_bfloat16 h = __float2bfloat16(v);
                    __nv_bfloat16 l = __float2bfloat16(v - __bfloat162float(h));
                    size_t o = (size_t)col * ldc + row;
                    Ch[o] = h;
                    Cl[o] = l;
                }
            }
    }
}

// ===========================================================================
// fp32 -> bf16 hi/lo split
// ===========================================================================
__global__ __launch_bounds__(256) void split_kernel(const float* __restrict__ in,
                                                    __nv_bfloat16* __restrict__ hi,
                                                    __nv_bfloat16* __restrict__ lo,
                                                    int n4)
{
    int i = blockIdx.x * 256 + threadIdx.x;
    if (i >= n4) return;
    float4 v = reinterpret_cast<const float4*>(in)[i];
    float vv[4] = {v.x, v.y, v.z, v.w};
    union { __nv_bfloat16 b[4]; uint2 u; } hb, lb;
#pragma unroll
    for (int j = 0; j < 4; j++) {
        __nv_bfloat16 h = __float2bfloat16(vv[j]);
        hb.b[j] = h;
        lb.b[j] = __float2bfloat16(vv[j] - __bfloat162float(h));
    }
    reinterpret_cast<uint2*>(hi)[i] = hb.u;
    reinterpret_cast<uint2*>(lo)[i] = lb.u;
}

// ===========================================================================
// Fused flash attention.
// grid (16 q-tiles, 16 bh); block 256 (8 warps, warp = 16 q-rows).
// Q (prescaled) in register fragments; K/V hi/lo double-buffered smem stages.
// Stage layout (64KB): Kh@0 Kl@16384 Vh@32768 Vl@49152
//   K tile: token t(0..63), dim d(0..127): row = t + (d>=64)*64, col = (d&63)*2
//   V tile: row = d(0..127), col = tok*2  (V^T source)
// Q (prologue, stage0): row = t + (d>=64)*128, col=(d&63)*2; Qh@0, Ql@32768
// ===========================================================================
#define FA_STAGE 65536
#define FA_SMEM  (2 * FA_STAGE)

__device__ __forceinline__ void fa_load_kv(const __nv_bfloat16* __restrict__ Kh,
                                           const __nv_bfloat16* __restrict__ Kl,
                                           const __nv_bfloat16* __restrict__ Vth,
                                           const __nv_bfloat16* __restrict__ Vtl,
                                           int tok0, int hd0, int btok,
                                           uint32_t st, int tid) {
    // K: 64 tokens x 128 dims (hi+lo)
#pragma unroll
    for (int i = 0; i < 4; i++) {
        int u = tid + i * 256;
        int t = u >> 4, c = u & 15;
        uint32_t off = SWZ128((((t + ((c >> 3) << 6)) << 7) | ((c & 7) << 4)));
        const __nv_bfloat16* g = Kh + (size_t)(btok + tok0 + t) * DIM + hd0 + (c << 3);
        CP_ASYNC16(st + off, g);
        g = Kl + (size_t)(btok + tok0 + t) * DIM + hd0 + (c << 3);
        CP_ASYNC16(st + 16384 + off, g);
    }
    // V^T: 128 dims x 64 tokens (hi+lo)
#pragma unroll
    for (int i = 0; i < 4; i++) {
        int u = tid + i * 256;
        int d = u >> 3, c = u & 7;
        uint32_t off = SWZ128(((d << 7) | (c << 4)));
        const __nv_bfloat16* g = Vth + (size_t)(hd0 + d) * TOK + btok + tok0 + (c << 3);
        CP_ASYNC16(st + 32768 + off, g);
        g = Vtl + (size_t)(hd0 + d) * TOK + btok + tok0 + (c << 3);
        CP_ASYNC16(st + 49152 + off, g);
    }
}

__global__ __launch_bounds__(256, 1) void attn_fused(
    const __nv_bfloat16* __restrict__ Qh, const __nv_bfloat16* __restrict__ Ql,
    const __nv_bfloat16* __restrict__ Kh, const __nv_bfloat16* __restrict__ Kl,
    const __nv_bfloat16* __restrict__ Vth, const __nv_bfloat16* __restrict__ Vtl,
    float* __restrict__ out)
{
    extern __shared__ char smem[];
    const uint32_t sb = smem_u32(smem);
    const int tid  = threadIdx.x;
    const int wid  = tid >> 5;
    const int lane = tid & 31;
    const int z = blockIdx.y, b = z >> 3, h = z & 7;
    const int bq0  = b * TSEQ + blockIdx.x * 128;
    const int hd0  = h * 128;
    const int btok = b * TSEQ;

    // ---- prologue: Q into stage0 ----
#pragma unroll
    for (int i = 0; i < 8; i++) {
        int u = tid + i * 256;
        int t = u >> 4, c = u & 15;
        uint32_t off = SWZ128((((t + ((c >> 3) << 7)) << 7) | ((c & 7) << 4)));
        const __nv_bfloat16* g = Qh + (size_t)(bq0 + t) * DIM + hd0 + (c << 3);
        CP_ASYNC16(sb + off, g);
        g = Ql + (size_t)(bq0 + t) * DIM + hd0 + (c << 3);
        CP_ASYNC16(sb + 32768 + off, g);
    }
    CP_COMMIT();
    // KV tile 0 -> stage1
    fa_load_kv(Kh, Kl, Vth, Vtl, 0, hd0, btok, sb + FA_STAGE, tid);
    CP_COMMIT();
    CP_WAIT1();              // Q done
    __syncthreads();

    // Q fragments -> registers
    uint32_t qfh[8][4], qfl[8][4];
#pragma unroll
    for (int kc = 0; kc < 8; kc++) {
        int row = wid * 16 + (lane & 7) + ((lane >> 3) & 1) * 8 + ((kc >> 2) << 7);
        int kb  = ((kc & 3) << 5) + ((lane >> 4) << 4);
        uint32_t off = SWZ128((row << 7) | kb);
        LDSM4(qfh[kc][0], qfh[kc][1], qfh[kc][2], qfh[kc][3], sb + off);
        LDSM4(qfl[kc][0], qfl[kc][1], qfl[kc][2], qfl[kc][3], sb + 32768 + off);
    }
    __syncthreads();
    // KV tile 1 -> stage0 (overwrites Q)
    fa_load_kv(Kh, Kl, Vth, Vtl, 64, hd0, btok, sb, tid);
    CP_COMMIT();

    float o[16][4];
#pragma unroll
    for (int i = 0; i < 16; i++)
#pragma unroll
        for (int q = 0; q < 4; q++) o[i][q] = 0.0f;
    float m0 = -INFINITY, m1 = -INFINITY, l0 = 0.0f, l1 = 0.0f;

    for (int it = 0; it < 32; it++) {
        const uint32_t st = sb + (1 - (it & 1)) * FA_STAGE;
        if (it < 31) { CP_WAIT1(); } else { CP_WAIT0(); }
        __syncthreads();

        // ---- S = Q K^T ----
        float s[8][4];
#pragma unroll
        for (int i = 0; i < 8; i++)
#pragma unroll
            for (int q = 0; q < 4; q++) s[i][q] = 0.0f;

#pragma unroll
        for (int kc = 0; kc < 8; kc++) {
            const int half = (kc >> 2) << 6;
            const int kb   = ((kc & 3) << 5) + (((lane >> 3) & 1) << 4);
#pragma unroll
            for (int nn = 0; nn < 4; nn++) {
                int row = nn * 16 + (lane & 7) + ((lane >> 4) << 3) + half;
                uint32_t off = SWZ128((row << 7) | kb);
                uint32_t bh0, bh1, bh2, bh3, bl0, bl1, bl2, bl3;
                LDSM4(bh0, bh1, bh2, bh3, st + off);
                LDSM4(bl0, bl1, bl2, bl3, st + 16384 + off);
                MMA16816(s[nn * 2],     qfh[kc], bh0, bh1);
                MMA16816(s[nn * 2],     qfl[kc], bh0, bh1);
                MMA16816(s[nn * 2],     qfh[kc], bl0, bl1);
                MMA16816(s[nn * 2 + 1], qfh[kc], bh2, bh3);
                MMA16816(s[nn * 2 + 1], qfl[kc], bh2, bh3);
                MMA16816(s[nn * 2 + 1], qfh[kc], bl2, bl3);
            }
        }

        // ---- online softmax (rows r=lane>>2 and r+8) ----
        float rmax0 = -INFINITY, rmax1 = -INFINITY;
#pragma unroll
        for (int nf = 0; nf < 8; nf++) {
            rmax0 = fmaxf(rmax0, fmaxf(s[nf][0], s[nf][1]));
            rmax1 = fmaxf(rmax1, fmaxf(s[nf][2], s[nf][3]));
        }
        rmax0 = fmaxf(rmax0, __shfl_xor_sync(0xffffffffu, rmax0, 1));
        rmax0 = fmaxf(rmax0, __shfl_xor_sync(0xffffffffu, rmax0, 2));
        rmax1 = fmaxf(rmax1, __shfl_xor_sync(0xffffffffu, rmax1, 1));
        rmax1 = fmaxf(rmax1, __shfl_xor_sync(0xffffffffu, rmax1, 2));
        const float mn0 = fmaxf(m0, rmax0), mn1 = fmaxf(m1, rmax1);
        const float a0 = __expf(m0 - mn0), a1 = __expf(m1 - mn1);
        float rs0 = 0.0f, rs1 = 0.0f;
#pragma unroll
        for (int nf = 0; nf < 8; nf++) {
            s[nf][0] = __expf(s[nf][0] - mn0);
            s[nf][1] = __expf(s[nf][1] - mn0);
            s[nf][2] = __expf(s[nf][2] - mn1);
            s[nf][3] = __expf(s[nf][3] - mn1);
            rs0 += s[nf][0] + s[nf][1];
            rs1 += s[nf][2] + s[nf][3];
        }
        rs0 += __shfl_xor_sync(0xffffffffu, rs0, 1);
        rs0 += __shfl_xor_sync(0xffffffffu, rs0, 2);
        rs1 += __shfl_xor_sync(0xffffffffu, rs1, 1);
        rs1 += __shfl_xor_sync(0xffffffffu, rs1, 2);
        l0 = l0 * a0 + rs0; l1 = l1 * a1 + rs1;
        m0 = mn0; m1 = mn1;
#pragma unroll
        for (int df = 0; df < 16; df++) {
            o[df][0] *= a0; o[df][1] *= a0;
            o[df][2] *= a1; o[df][3] *= a1;
        }

        // ---- P -> bf16 hi/lo A-fragments (C-frag layout == A-frag layout) ----
        uint32_t ph[4][4], pl[4][4];
#pragma unroll
        for (int kv = 0; kv < 4; kv++) {
            split2(s[kv * 2][0],     s[kv * 2][1],     ph[kv][0], pl[kv][0]);
            split2(s[kv * 2][2],     s[kv * 2][3],     ph[kv][1], pl[kv][1]);
            split2(s[kv * 2 + 1][0], s[kv * 2 + 1][1], ph[kv][2], pl[kv][2]);
            split2(s[kv * 2 + 1][2], s[kv * 2 + 1][3], ph[kv][3], pl[kv][3]);
        }

        // ---- O += P V ----
#pragma unroll
        for (int kv = 0; kv < 4; kv++) {
            const int kb = (kv << 5) + (((lane >> 3) & 1) << 4);
#pragma unroll
            for (int ddf = 0; ddf < 8; ddf++) {
                int row = ddf * 16 + (lane & 7) + ((lane >> 4) << 3);
                uint32_t off = SWZ128((row << 7) | kb);
                uint32_t vh0, vh1, vh2, vh3, vl0, vl1, vl2, vl3;
                LDSM4(vh0, vh1, vh2, vh3, st + 32768 + off);
                LDSM4(vl0, vl1, vl2, vl3, st + 49152 + off);
                MMA16816(o[ddf * 2],     ph[kv], vh0, vh1);
                MMA16816(o[ddf * 2],     pl[kv], vh0, vh1);
                MMA16816(o[ddf * 2],     ph[kv], vl0, vl1);
                MMA16816(o[ddf * 2 + 1], ph[kv], vh2, vh3);
                MMA16816(o[ddf * 2 + 1], pl[kv], vh2, vh3);
                MMA16816(o[ddf * 2 + 1], ph[kv], vl2, vl3);
            }
        }

        __syncthreads();
        if (it + 2 < 32) {
            fa_load_kv(Kh, Kl, Vth, Vtl, (it + 2) * 64, hd0, btok, st, tid);
            CP_COMMIT();
        }
    }

    // ---- epilogue: normalize & store ----
    const float inv0 = 1.0f / l0, inv1 = 1.0f / l1;
    const int r0 = wid * 16 + (lane >> 2);
#pragma unroll
    for (int df = 0; df < 16; df++) {
        const int d = hd0 + df * 8 + 2 * (lane & 3);
        float* p0 = out + (size_t)(bq0 + r0) * DIM + d;
        float* p1 = out + (size_t)(bq0 + r0 + 8) * DIM + d;
        *reinterpret_cast<float2*>(p0) = make_float2(o[df][0] * inv0, o[df][1] * inv0);
        *reinterpret_cast<float2*>(p1) = make_float2(o[df][2] * inv1, o[df][3] * inv1);
    }
}

// ===========================================================================
// Launch
// ===========================================================================
extern "C" void kernel_launch(void* const* d_in, const int* in_sizes, int n_in,
                              void* d_out, int out_size)
{
    const float* query = (const float*)d_in[0];
    const float* keys  = (const float*)d_in[1];
    const float* Wq    = (const float*)d_in[2];
    const float* Wk    = (const float*)d_in[3];
    const float* Wv    = (const float*)d_in[4];
    float* out = (float*)d_out;

    __nv_bfloat16 *qh, *ql, *kh, *kl, *Wqh, *Wql, *Wkh, *Wkl, *Wvh, *Wvl;
    __nv_bfloat16 *Qh, *Ql, *Kh, *Kl, *Vth, *Vtl;
    cudaGetSymbolAddress((void**)&qh, g_qh);   cudaGetSymbolAddress((void**)&ql, g_ql);
    cudaGetSymbolAddress((void**)&kh, g_kh);   cudaGetSymbolAddress((void**)&kl, g_kl);
    cudaGetSymbolAddress((void**)&Wqh, g_Wqh); cudaGetSymbolAddress((void**)&Wql, g_Wql);
    cudaGetSymbolAddress((void**)&Wkh, g_Wkh); cudaGetSymbolAddress((void**)&Wkl, g_Wkl);
    cudaGetSymbolAddress((void**)&Wvh, g_Wvh); cudaGetSymbolAddress((void**)&Wvl, g_Wvl);
    cudaGetSymbolAddress((void**)&Qh, g_Qh);   cudaGetSymbolAddress((void**)&Ql, g_Ql);
    cudaGetSymbolAddress((void**)&Kh, g_Kh);   cudaGetSymbolAddress((void**)&Kl, g_Kl);
    cudaGetSymbolAddress((void**)&Vth, g_Vth); cudaGetSymbolAddress((void**)&Vtl, g_Vtl);

    cudaFuncSetAttribute(gemm_proj, cudaFuncAttributeMaxDynamicSharedMemorySize,
                         G_SMEM_TOTAL);
    cudaFuncSetAttribute(attn_fused, cudaFuncAttributeMaxDynamicSharedMemorySize,
                         FA_SMEM);

    // 1) split inputs
    split_kernel<<<(TOK * DIM / 4 + 255) / 256, 256>>>(query, qh, ql, TOK * DIM / 4);
    split_kernel<<<(TOK * DIM / 4 + 255) / 256, 256>>>(keys,  kh, kl, TOK * DIM / 4);
    split_kernel<<<(DIM * DIM / 4 + 255) / 256, 256>>>(Wq, Wqh, Wql, DIM * DIM / 4);
    split_kernel<<<(DIM * DIM / 4 + 255) / 256, 256>>>(Wk, Wkh, Wkl, DIM * DIM / 4);
    split_kernel<<<(DIM * DIM / 4 + 255) / 256, 256>>>(Wv, Wvh, Wvl, DIM * DIM / 4);

    // 2) projections (Q prescaled by 2^-5; V stored transposed)
    dim3 gp(DIM / 128, TOK / 128);
    gemm_proj<<<gp, 256, G_SMEM_TOTAL>>>(qh, ql, Wqh, Wql, Qh, Ql, DIM, 1, QSCALE);
    gemm_proj<<<gp, 256, G_SMEM_TOTAL>>>(kh, kl, Wkh, Wkl, Kh, Kl, DIM, 1, 1.0f);
    gemm_proj<<<gp, 256, G_SMEM_TOTAL>>>(kh, kl, Wvh, Wvl, Vth, Vtl, TOK, 2, 1.0f);

    // 3) fused flash attention -> out
    dim3 ga(TSEQ / 128, NBH);
    attn_fused<<<ga, 256, FA_SMEM>>>(Qh, Ql, Kh, Kl, Vth, Vtl, out);
}

// round 5
// speedup vs baseline: 9.2397x; 2.2031x over previous
#include <cuda_runtime.h>
#include <cuda_fp16.h>
#include <stdint.h>

// ===========================================================================
// Problem constants
// ===========================================================================
#define TOK   4096      // 2*2048 tokens
#define DIM   1024
#define TSEQ  2048
#define NBH   16
#define QSCALE 0.03125f // 1/sqrt(1024) = 2^-5

// ===========================================================================
// Device scratch (allocation-free)
// ===========================================================================
__device__ __align__(16) __half g_q16[TOK * DIM];     // query fp16
__device__ __align__(16) __half g_k16[TOK * DIM];     // keys fp16
__device__ __align__(16) __half g_Wq16[DIM * DIM];
__device__ __align__(16) __half g_Wk16[DIM * DIM];
__device__ __align__(16) __half g_Wv16[DIM * DIM];
__device__ __align__(16) __half g_Q16[TOK * DIM];     // Q proj (prescaled 2^-5)
__device__ __align__(16) __half g_K16[TOK * DIM];     // K proj
__device__ __align__(16) __half g_Vt16[DIM * TOK];    // V^T proj

// ===========================================================================
// Helpers
// ===========================================================================
__device__ __forceinline__ uint32_t smem_u32(const void* p) {
    uint32_t a;
    asm("{ .reg .u64 t; cvta.to.shared.u64 t, %1; cvt.u32.u64 %0, t; }" : "=r"(a) : "l"(p));
    return a;
}
#define SWZ128(off) ((off) ^ (((off) >> 3) & 0x70))

#define LDSM4(r0, r1, r2, r3, addr) \
    asm volatile("ldmatrix.sync.aligned.m8n8.x4.shared.b16 {%0,%1,%2,%3}, [%4];" \
                 : "=r"(r0), "=r"(r1), "=r"(r2), "=r"(r3) : "r"(addr))

#define MMA16816(d, a, b0, b1) \
    asm volatile("mma.sync.aligned.m16n8k16.row.col.f32.f16.f16.f32 " \
                 "{%0,%1,%2,%3}, {%4,%5,%6,%7}, {%8,%9}, {%0,%1,%2,%3};" \
                 : "+f"((d)[0]), "+f"((d)[1]), "+f"((d)[2]), "+f"((d)[3]) \
                 : "r"((a)[0]), "r"((a)[1]), "r"((a)[2]), "r"((a)[3]), \
                   "r"(b0), "r"(b1))

#define CP_ASYNC16(dst, src) \
    asm volatile("cp.async.cg.shared.global [%0], [%1], 16;" :: "r"(dst), "l"(src))
#define CP_COMMIT()  asm volatile("cp.async.commit_group;" ::: "memory")
#define CP_WAIT0()   asm volatile("cp.async.wait_group 0;" ::: "memory")
#define CP_WAIT1()   asm volatile("cp.async.wait_group 1;" ::: "memory")

__device__ __forceinline__ uint32_t packh2(float a, float b) {
    __half2 h = __floats2half2_rn(a, b);
    return *reinterpret_cast<uint32_t*>(&h);
}

// ===========================================================================
// Projection GEMM (NT): C[m,n] = sum_k A[m,k]*B[n,k], fp16 single, 1 MMA.
// grid (N/128=8, M/128=32); block 256; lda=ldb=DIM; K=DIM.
// mode 1: fp16 store (scaled); mode 2: fp16 transposed store via smem (scaled)
// Stage: A 16KB + B 16KB = 32KB; 2 stages = 64KB.
// ===========================================================================
#define G_STAGE      32768
#define G_SMEM_TOTAL (2 * G_STAGE)

__device__ __forceinline__ void cpa_tile(const __half* __restrict__ src,
                                         int rowBase, int kt,
                                         uint32_t dstBase, int tid) {
#pragma unroll
    for (int i = 0; i < 4; i++) {
        int u = tid + i * 256;          // 0..1023
        int r = u >> 3;                 // row 0..127
        int cb = (u & 7) << 4;          // byte col 0..112
        uint32_t dst = dstBase + SWZ128((r << 7) | cb);
        const void* gsrc = src + (size_t)(rowBase + r) * DIM + kt + ((u & 7) << 3);
        CP_ASYNC16(dst, gsrc);
    }
}

__global__ __launch_bounds__(256, 1) void gemm_proj(
    const __half* __restrict__ A, const __half* __restrict__ B,
    __half* C, int ldc, int mode, float cscale)
{
    extern __shared__ char smem[];
    const uint32_t sb = smem_u32(smem);
    const int tid  = threadIdx.x;
    const int wid  = tid >> 5;
    const int lane = tid & 31;
    const int wm   = wid & 3;          // 4 warps along M
    const int wn   = wid >> 2;         // 2 warps along N
    const int nBase = blockIdx.x * 128;
    const int mBase = blockIdx.y * 128;

    const int nc = DIM >> 6;

    cpa_tile(A, mBase, 0, sb,         tid);
    cpa_tile(B, nBase, 0, sb + 16384, tid);
    CP_COMMIT();

    float acc[2][8][4];
#pragma unroll
    for (int i = 0; i < 2; i++)
#pragma unroll
        for (int j = 0; j < 8; j++)
#pragma unroll
            for (int q = 0; q < 4; q++) acc[i][j][q] = 0.0f;

    const int arow = wm * 32 + ((lane >> 3) & 1) * 8 + (lane & 7);
    const int akb  = (lane >> 4) << 4;
    const int brow = wn * 64 + ((lane >> 4) << 3) + (lane & 7);
    const int bkb  = ((lane >> 3) & 1) << 4;

    for (int c = 0; c < nc; c++) {
        const int s = c & 1;
        if (c + 1 < nc) {
            const uint32_t st = sb + (s ^ 1) * G_STAGE;
            const int kt = (c + 1) << 6;
            cpa_tile(A, mBase, kt, st,         tid);
            cpa_tile(B, nBase, kt, st + 16384, tid);
            CP_COMMIT();
            CP_WAIT1();
        } else {
            CP_WAIT0();
        }
        __syncthreads();

        const uint32_t Ab = sb + s * G_STAGE;
        const uint32_t Bb = Ab + 16384;

#pragma unroll
        for (int kk = 0; kk < 4; kk++) {
            const int kb = kk * 32;
            uint32_t af[2][4];
#pragma unroll
            for (int mi = 0; mi < 2; mi++) {
                const int r = arow + mi * 16;
                const uint32_t off = SWZ128((r << 7) | (kb + akb));
                LDSM4(af[mi][0], af[mi][1], af[mi][2], af[mi][3], Ab + off);
            }
#pragma unroll
            for (int nn = 0; nn < 4; nn++) {
                const int n = brow + nn * 16;
                const uint32_t off = SWZ128((n << 7) | (kb + bkb));
                uint32_t b0, b1, b2, b3;
                LDSM4(b0, b1, b2, b3, Bb + off);
#pragma unroll
                for (int mi = 0; mi < 2; mi++) {
                    MMA16816(acc[mi][nn * 2],     af[mi], b0, b1);
                    MMA16816(acc[mi][nn * 2 + 1], af[mi], b2, b3);
                }
            }
        }
        __syncthreads();
    }

    if (mode == 1) {
        const int erow = mBase + wm * 32 + (lane >> 2);
        const int ecol = nBase + wn * 64 + 2 * (lane & 3);
#pragma unroll
        for (int mi = 0; mi < 2; mi++)
#pragma unroll
            for (int ni = 0; ni < 8; ni++) {
                const float* a = acc[mi][ni];
#pragma unroll
                for (int half = 0; half < 2; half++) {
                    uint32_t hp = packh2(a[half * 2] * cscale, a[half * 2 + 1] * cscale);
                    size_t o = (size_t)(erow + mi * 16 + half * 8) * ldc + ecol + ni * 8;
                    *reinterpret_cast<uint32_t*>(C + o) = hp;
                }
            }
    } else {
        // transposed store via smem: T[n][m], stride 136 halves
        __half* T = reinterpret_cast<__half*>(smem);
        const int lrow = wm * 32 + (lane >> 2);
        const int lcol = wn * 64 + 2 * (lane & 3);
#pragma unroll
        for (int mi = 0; mi < 2; mi++)
#pragma unroll
            for (int ni = 0; ni < 8; ni++) {
                const float* a = acc[mi][ni];
#pragma unroll
                for (int q = 0; q < 4; q++) {
                    int row = lrow + mi * 16 + (q >> 1) * 8;
                    int col = lcol + ni * 8 + (q & 1);
                    T[col * 136 + row] = __float2half_rn(a[q] * cscale);
                }
            }
        __syncthreads();
#pragma unroll
        for (int ch = 0; ch < 8; ch++) {
            int idx = tid + ch * 256;   // 0..2047
            int n  = idx >> 4;
            int m8 = (idx & 15) << 3;
            uint4 v = *reinterpret_cast<uint4*>(T + n * 136 + m8);
            *reinterpret_cast<uint4*>(C + (size_t)(nBase + n) * ldc + mBase + m8) = v;
        }
    }
}

// ===========================================================================
// fp32 -> fp16 convert
// ===========================================================================
__global__ __launch_bounds__(256) void tohalf_kernel(const float* __restrict__ in,
                                                     __half* __restrict__ out, int n4)
{
    int i = blockIdx.x * 256 + threadIdx.x;
    if (i >= n4) return;
    float4 v = reinterpret_cast<const float4*>(in)[i];
    uint2 u;
    u.x = packh2(v.x, v.y);
    u.y = packh2(v.z, v.w);
    reinterpret_cast<uint2*>(out)[i] = u;
}

// ===========================================================================
// Fused flash attention, fp16 single.
// grid (16 q-tiles, 16 bh); block 256 (8 warps, warp = 16 q-rows).
// Stage (32KB): K@0 (64tok x 128d), Vt@16384 (128d x 64tok). 2 stages.
// Q prologue uses stage0 folded 256x64-dim layout (32KB), then overwritten.
// ===========================================================================
#define FA_STAGE 32768
#define FA_SMEM  (2 * FA_STAGE)

__device__ __forceinline__ void fa_load_kv(const __half* __restrict__ K,
                                           const __half* __restrict__ Vt,
                                           int tok0, int hd0, int btok,
                                           uint32_t st, int tid) {
    // K: 64 tokens x 128 dims, folded: row = t + (d>=64)*64, col=(d&63)*2B*...
#pragma unroll
    for (int i = 0; i < 4; i++) {
        int u = tid + i * 256;
        int t = u >> 4, c = u & 15;
        uint32_t off = SWZ128((((t + ((c >> 3) << 6)) << 7) | ((c & 7) << 4)));
        const __half* g = K + (size_t)(btok + tok0 + t) * DIM + hd0 + (c << 3);
        CP_ASYNC16(st + off, g);
    }
    // V^T: 128 dims x 64 tokens
#pragma unroll
    for (int i = 0; i < 4; i++) {
        int u = tid + i * 256;
        int d = u >> 3, c = u & 7;
        uint32_t off = SWZ128(((d << 7) | (c << 4)));
        const __half* g = Vt + (size_t)(hd0 + d) * TOK + btok + tok0 + (c << 3);
        CP_ASYNC16(st + 16384 + off, g);
    }
}

__global__ __launch_bounds__(256, 1) void attn_fused(
    const __half* __restrict__ Q, const __half* __restrict__ K,
    const __half* __restrict__ Vt, float* __restrict__ out)
{
    extern __shared__ char smem[];
    const uint32_t sb = smem_u32(smem);
    const int tid  = threadIdx.x;
    const int wid  = tid >> 5;
    const int lane = tid & 31;
    const int z = blockIdx.y, b = z >> 3, h = z & 7;
    const int bq0  = b * TSEQ + blockIdx.x * 128;
    const int hd0  = h * 128;
    const int btok = b * TSEQ;

    // ---- prologue: Q (128x128) into stage0, folded 256-row layout ----
#pragma unroll
    for (int i = 0; i < 8; i++) {
        int u = tid + i * 256;          // 0..2047
        int t = u >> 4, c = u & 15;
        uint32_t off = SWZ128((((t + ((c >> 3) << 7)) << 7) | ((c & 7) << 4)));
        const __half* g = Q + (size_t)(bq0 + t) * DIM + hd0 + (c << 3);
        CP_ASYNC16(sb + off, g);
    }
    CP_COMMIT();
    fa_load_kv(K, Vt, 0, hd0, btok, sb + FA_STAGE, tid);
    CP_COMMIT();
    CP_WAIT1();              // Q done
    __syncthreads();

    // Q fragments -> registers
    uint32_t qf[8][4];
#pragma unroll
    for (int kc = 0; kc < 8; kc++) {
        int row = wid * 16 + (lane & 7) + ((lane >> 3) & 1) * 8 + ((kc >> 2) << 7);
        int kb  = ((kc & 3) << 5) + ((lane >> 4) << 4);
        uint32_t off = SWZ128((row << 7) | kb);
        LDSM4(qf[kc][0], qf[kc][1], qf[kc][2], qf[kc][3], sb + off);
    }
    __syncthreads();
    fa_load_kv(K, Vt, 64, hd0, btok, sb, tid);   // tile 1 -> stage0
    CP_COMMIT();

    float o[16][4];
#pragma unroll
    for (int i = 0; i < 16; i++)
#pragma unroll
        for (int q = 0; q < 4; q++) o[i][q] = 0.0f;
    float m0 = -INFINITY, m1 = -INFINITY, l0 = 0.0f, l1 = 0.0f;

    for (int it = 0; it < 32; it++) {
        const uint32_t st = sb + (1 - (it & 1)) * FA_STAGE;
        if (it < 31) { CP_WAIT1(); } else { CP_WAIT0(); }
        __syncthreads();

        // ---- S = Q K^T ----
        float s[8][4];
#pragma unroll
        for (int i = 0; i < 8; i++)
#pragma unroll
            for (int q = 0; q < 4; q++) s[i][q] = 0.0f;

#pragma unroll
        for (int kc = 0; kc < 8; kc++) {
            const int half = (kc >> 2) << 6;
            const int kb   = ((kc & 3) << 5) + (((lane >> 3) & 1) << 4);
#pragma unroll
            for (int nn = 0; nn < 4; nn++) {
                int row = nn * 16 + (lane & 7) + ((lane >> 4) << 3) + half;
                uint32_t off = SWZ128((row << 7) | kb);
                uint32_t b0, b1, b2, b3;
                LDSM4(b0, b1, b2, b3, st + off);
                MMA16816(s[nn * 2],     qf[kc], b0, b1);
                MMA16816(s[nn * 2 + 1], qf[kc], b2, b3);
            }
        }

        // ---- online softmax (rows r=lane>>2 and r+8) ----
        float rmax0 = -INFINITY, rmax1 = -INFINITY;
#pragma unroll
        for (int nf = 0; nf < 8; nf++) {
            rmax0 = fmaxf(rmax0, fmaxf(s[nf][0], s[nf][1]));
            rmax1 = fmaxf(rmax1, fmaxf(s[nf][2], s[nf][3]));
        }
        rmax0 = fmaxf(rmax0, __shfl_xor_sync(0xffffffffu, rmax0, 1));
        rmax0 = fmaxf(rmax0, __shfl_xor_sync(0xffffffffu, rmax0, 2));
        rmax1 = fmaxf(rmax1, __shfl_xor_sync(0xffffffffu, rmax1, 1));
        rmax1 = fmaxf(rmax1, __shfl_xor_sync(0xffffffffu, rmax1, 2));
        const float mn0 = fmaxf(m0, rmax0), mn1 = fmaxf(m1, rmax1);
        const float a0 = __expf(m0 - mn0), a1 = __expf(m1 - mn1);
        float rs0 = 0.0f, rs1 = 0.0f;
#pragma unroll
        for (int nf = 0; nf < 8; nf++) {
            s[nf][0] = __expf(s[nf][0] - mn0);
            s[nf][1] = __expf(s[nf][1] - mn0);
            s[nf][2] = __expf(s[nf][2] - mn1);
            s[nf][3] = __expf(s[nf][3] - mn1);
            rs0 += s[nf][0] + s[nf][1];
            rs1 += s[nf][2] + s[nf][3];
        }
        rs0 += __shfl_xor_sync(0xffffffffu, rs0, 1);
        rs0 += __shfl_xor_sync(0xffffffffu, rs0, 2);
        rs1 += __shfl_xor_sync(0xffffffffu, rs1, 1);
        rs1 += __shfl_xor_sync(0xffffffffu, rs1, 2);
        l0 = l0 * a0 + rs0; l1 = l1 * a1 + rs1;
        m0 = mn0; m1 = mn1;
#pragma unroll
        for (int df = 0; df < 16; df++) {
            o[df][0] *= a0; o[df][1] *= a0;
            o[df][2] *= a1; o[df][3] *= a1;
        }

        // ---- P -> fp16 A-fragments (C-frag layout == A-frag layout) ----
        uint32_t p[4][4];
#pragma unroll
        for (int kv = 0; kv < 4; kv++) {
            p[kv][0] = packh2(s[kv * 2][0],     s[kv * 2][1]);
            p[kv][1] = packh2(s[kv * 2][2],     s[kv * 2][3]);
            p[kv][2] = packh2(s[kv * 2 + 1][0], s[kv * 2 + 1][1]);
            p[kv][3] = packh2(s[kv * 2 + 1][2], s[kv * 2 + 1][3]);
        }

        // ---- O += P V ----
#pragma unroll
        for (int kv = 0; kv < 4; kv++) {
            const int kb = (kv << 5) + (((lane >> 3) & 1) << 4);
#pragma unroll
            for (int ddf = 0; ddf < 8; ddf++) {
                int row = ddf * 16 + (lane & 7) + ((lane >> 4) << 3);
                uint32_t off = SWZ128((row << 7) | kb);
                uint32_t v0, v1, v2, v3;
                LDSM4(v0, v1, v2, v3, st + 16384 + off);
                MMA16816(o[ddf * 2],     p[kv], v0, v1);
                MMA16816(o[ddf * 2 + 1], p[kv], v2, v3);
            }
        }

        __syncthreads();
        if (it + 2 < 32) {
            fa_load_kv(K, Vt, (it + 2) * 64, hd0, btok, st, tid);
            CP_COMMIT();
        }
    }

    // ---- epilogue: normalize & store ----
    const float inv0 = 1.0f / l0, inv1 = 1.0f / l1;
    const int r0 = wid * 16 + (lane >> 2);
#pragma unroll
    for (int df = 0; df < 16; df++) {
        const int d = hd0 + df * 8 + 2 * (lane & 3);
        float* p0 = out + (size_t)(bq0 + r0) * DIM + d;
        float* p1 = out + (size_t)(bq0 + r0 + 8) * DIM + d;
        *reinterpret_cast<float2*>(p0) = make_float2(o[df][0] * inv0, o[df][1] * inv0);
        *reinterpret_cast<float2*>(p1) = make_float2(o[df][2] * inv1, o[df][3] * inv1);
    }
}

// ===========================================================================
// Launch
// ===========================================================================
extern "C" void kernel_launch(void* const* d_in, const int* in_sizes, int n_in,
                              void* d_out, int out_size)
{
    const float* query = (const float*)d_in[0];
    const float* keys  = (const float*)d_in[1];
    const float* Wq    = (const float*)d_in[2];
    const float* Wk    = (const float*)d_in[3];
    const float* Wv    = (const float*)d_in[4];
    float* out = (float*)d_out;

    __half *q16, *k16, *Wq16, *Wk16, *Wv16, *Q16, *K16, *Vt16;
    cudaGetSymbolAddress((void**)&q16, g_q16);
    cudaGetSymbolAddress((void**)&k16, g_k16);
    cudaGetSymbolAddress((void**)&Wq16, g_Wq16);
    cudaGetSymbolAddress((void**)&Wk16, g_Wk16);
    cudaGetSymbolAddress((void**)&Wv16, g_Wv16);
    cudaGetSymbolAddress((void**)&Q16, g_Q16);
    cudaGetSymbolAddress((void**)&K16, g_K16);
    cudaGetSymbolAddress((void**)&Vt16, g_Vt16);

    cudaFuncSetAttribute(gemm_proj, cudaFuncAttributeMaxDynamicSharedMemorySize,
                         G_SMEM_TOTAL);
    cudaFuncSetAttribute(attn_fused, cudaFuncAttributeMaxDynamicSharedMemorySize,
                         FA_SMEM);

    // 1) convert inputs to fp16
    tohalf_kernel<<<TOK * DIM / 4 / 256, 256>>>(query, q16, TOK * DIM / 4);
    tohalf_kernel<<<TOK * DIM / 4 / 256, 256>>>(keys,  k16, TOK * DIM / 4);
    tohalf_kernel<<<DIM * DIM / 4 / 256, 256>>>(Wq, Wq16, DIM * DIM / 4);
    tohalf_kernel<<<DIM * DIM / 4 / 256, 256>>>(Wk, Wk16, DIM * DIM / 4);
    tohalf_kernel<<<DIM * DIM / 4 / 256, 256>>>(Wv, Wv16, DIM * DIM / 4);

    // 2) projections (Q prescaled by 2^-5; V stored transposed)
    dim3 gp(DIM / 128, TOK / 128);
    gemm_proj<<<gp, 256, G_SMEM_TOTAL>>>(q16, Wq16, Q16, DIM, 1, QSCALE);
    gemm_proj<<<gp, 256, G_SMEM_TOTAL>>>(k16, Wk16, K16, DIM, 1, 1.0f);
    gemm_proj<<<gp, 256, G_SMEM_TOTAL>>>(k16, Wv16, Vt16, TOK, 2, 1.0f);

    // 3) fused flash attention -> out
    dim3 ga(TSEQ / 128, NBH);
    attn_fused<<<ga, 256, FA_SMEM>>>(Q16, K16, Vt16, out);
}

// round 6
// speedup vs baseline: 10.2522x; 1.1096x over previous
#include <cuda_runtime.h>
#include <cuda_fp16.h>
#include <stdint.h>

// ===========================================================================
// Problem constants
// ===========================================================================
#define TOK   4096      // 2*2048 tokens
#define DIM   1024
#define TSEQ  2048
#define NBH   16
#define QSCALE 0.03125f // 1/sqrt(1024) = 2^-5

// ===========================================================================
// Device scratch (allocation-free)
// ===========================================================================
__device__ __align__(16) __half g_q16[TOK * DIM];
__device__ __align__(16) __half g_k16[TOK * DIM];
__device__ __align__(16) __half g_Wq16[DIM * DIM];
__device__ __align__(16) __half g_Wk16[DIM * DIM];
__device__ __align__(16) __half g_Wv16[DIM * DIM];
__device__ __align__(16) __half g_Q16[TOK * DIM];     // Q proj (prescaled 2^-5)
__device__ __align__(16) __half g_K16[TOK * DIM];     // K proj
__device__ __align__(16) __half g_Vt16[DIM * TOK];    // V^T proj

// ===========================================================================
// Helpers
// ===========================================================================
__device__ __forceinline__ uint32_t smem_u32(const void* p) {
    uint32_t a;
    asm("{ .reg .u64 t; cvta.to.shared.u64 t, %1; cvt.u32.u64 %0, t; }" : "=r"(a) : "l"(p));
    return a;
}
#define SWZ128(off) ((off) ^ (((off) >> 3) & 0x70))

#define LDSM4(r0, r1, r2, r3, addr) \
    asm volatile("ldmatrix.sync.aligned.m8n8.x4.shared.b16 {%0,%1,%2,%3}, [%4];" \
                 : "=r"(r0), "=r"(r1), "=r"(r2), "=r"(r3) : "r"(addr))

// fp32-accumulate MMA (projections, PV)
#define MMA16816(d, a, b0, b1) \
    asm volatile("mma.sync.aligned.m16n8k16.row.col.f32.f16.f16.f32 " \
                 "{%0,%1,%2,%3}, {%4,%5,%6,%7}, {%8,%9}, {%0,%1,%2,%3};" \
                 : "+f"((d)[0]), "+f"((d)[1]), "+f"((d)[2]), "+f"((d)[3]) \
                 : "r"((a)[0]), "r"((a)[1]), "r"((a)[2]), "r"((a)[3]), \
                   "r"(b0), "r"(b1))

// fp16-accumulate MMA (S = QK^T only; 8 chunk-roundings @ |S|~0.12 -> ~1e-4)
#define MMA16816H(d, a, b0, b1) \
    asm volatile("mma.sync.aligned.m16n8k16.row.col.f16.f16.f16.f16 " \
                 "{%0,%1}, {%2,%3,%4,%5}, {%6,%7}, {%0,%1};" \
                 : "+r"((d)[0]), "+r"((d)[1]) \
                 : "r"((a)[0]), "r"((a)[1]), "r"((a)[2]), "r"((a)[3]), \
                   "r"(b0), "r"(b1))

#define CP_ASYNC16(dst, src) \
    asm volatile("cp.async.cg.shared.global [%0], [%1], 16;" :: "r"(dst), "l"(src))
#define CP_COMMIT()  asm volatile("cp.async.commit_group;" ::: "memory")
#define CP_WAIT0()   asm volatile("cp.async.wait_group 0;" ::: "memory")
#define CP_WAIT1()   asm volatile("cp.async.wait_group 1;" ::: "memory")

__device__ __forceinline__ uint32_t packh2(float a, float b) {
    __half2 h = __floats2half2_rn(a, b);
    return *reinterpret_cast<uint32_t*>(&h);
}

// ===========================================================================
// Projection GEMM (NT): C[m,n] = sum_k A[m,k]*B[n,k], fp16 in, fp32 acc.
// grid (N/128=8, M/128=32); block 256, occupancy 2.
// mode 1: fp16 store (scaled); mode 2: fp16 transposed store via smem
// ===========================================================================
#define G_STAGE      32768
#define G_SMEM_TOTAL (2 * G_STAGE)

__device__ __forceinline__ void cpa_tile(const __half* __restrict__ src,
                                         int rowBase, int kt,
                                         uint32_t dstBase, int tid) {
#pragma unroll
    for (int i = 0; i < 4; i++) {
        int u = tid + i * 256;          // 0..1023
        int r = u >> 3;                 // row 0..127
        int cb = (u & 7) << 4;          // byte col 0..112
        uint32_t dst = dstBase + SWZ128((r << 7) | cb);
        const void* gsrc = src + (size_t)(rowBase + r) * DIM + kt + ((u & 7) << 3);
        CP_ASYNC16(dst, gsrc);
    }
}

__global__ __launch_bounds__(256, 2) void gemm_proj(
    const __half* __restrict__ A, const __half* __restrict__ B,
    __half* C, int ldc, int mode, float cscale)
{
    extern __shared__ char smem[];
    const uint32_t sb = smem_u32(smem);
    const int tid  = threadIdx.x;
    const int wid  = tid >> 5;
    const int lane = tid & 31;
    const int wm   = wid & 3;
    const int wn   = wid >> 2;
    const int nBase = blockIdx.x * 128;
    const int mBase = blockIdx.y * 128;

    const int nc = DIM >> 6;

    cpa_tile(A, mBase, 0, sb,         tid);
    cpa_tile(B, nBase, 0, sb + 16384, tid);
    CP_COMMIT();

    float acc[2][8][4];
#pragma unroll
    for (int i = 0; i < 2; i++)
#pragma unroll
        for (int j = 0; j < 8; j++)
#pragma unroll
            for (int q = 0; q < 4; q++) acc[i][j][q] = 0.0f;

    const int arow = wm * 32 + ((lane >> 3) & 1) * 8 + (lane & 7);
    const int akb  = (lane >> 4) << 4;
    const int brow = wn * 64 + ((lane >> 4) << 3) + (lane & 7);
    const int bkb  = ((lane >> 3) & 1) << 4;

    for (int c = 0; c < nc; c++) {
        const int s = c & 1;
        if (c + 1 < nc) {
            const uint32_t st = sb + (s ^ 1) * G_STAGE;
            const int kt = (c + 1) << 6;
            cpa_tile(A, mBase, kt, st,         tid);
            cpa_tile(B, nBase, kt, st + 16384, tid);
            CP_COMMIT();
            CP_WAIT1();
        } else {
            CP_WAIT0();
        }
        __syncthreads();

        const uint32_t Ab = sb + s * G_STAGE;
        const uint32_t Bb = Ab + 16384;

#pragma unroll
        for (int kk = 0; kk < 4; kk++) {
            const int kb = kk * 32;
            uint32_t af[2][4];
#pragma unroll
            for (int mi = 0; mi < 2; mi++) {
                const int r = arow + mi * 16;
                const uint32_t off = SWZ128((r << 7) | (kb + akb));
                LDSM4(af[mi][0], af[mi][1], af[mi][2], af[mi][3], Ab + off);
            }
#pragma unroll
            for (int nn = 0; nn < 4; nn++) {
                const int n = brow + nn * 16;
                const uint32_t off = SWZ128((n << 7) | (kb + bkb));
                uint32_t b0, b1, b2, b3;
                LDSM4(b0, b1, b2, b3, Bb + off);
#pragma unroll
                for (int mi = 0; mi < 2; mi++) {
                    MMA16816(acc[mi][nn * 2],     af[mi], b0, b1);
                    MMA16816(acc[mi][nn * 2 + 1], af[mi], b2, b3);
                }
            }
        }
        __syncthreads();
    }

    if (mode == 1) {
        const int erow = mBase + wm * 32 + (lane >> 2);
        const int ecol = nBase + wn * 64 + 2 * (lane & 3);
#pragma unroll
        for (int mi = 0; mi < 2; mi++)
#pragma unroll
            for (int ni = 0; ni < 8; ni++) {
                const float* a = acc[mi][ni];
#pragma unroll
                for (int half = 0; half < 2; half++) {
                    uint32_t hp = packh2(a[half * 2] * cscale, a[half * 2 + 1] * cscale);
                    size_t o = (size_t)(erow + mi * 16 + half * 8) * ldc + ecol + ni * 8;
                    *reinterpret_cast<uint32_t*>(C + o) = hp;
                }
            }
    } else {
        // transposed store via smem: T[n][m], stride 136 halves
        __half* T = reinterpret_cast<__half*>(smem);
        const int lrow = wm * 32 + (lane >> 2);
        const int lcol = wn * 64 + 2 * (lane & 3);
#pragma unroll
        for (int mi = 0; mi < 2; mi++)
#pragma unroll
            for (int ni = 0; ni < 8; ni++) {
                const float* a = acc[mi][ni];
#pragma unroll
                for (int q = 0; q < 4; q++) {
                    int row = lrow + mi * 16 + (q >> 1) * 8;
                    int col = lcol + ni * 8 + (q & 1);
                    T[col * 136 + row] = __float2half_rn(a[q] * cscale);
                }
            }
        __syncthreads();
#pragma unroll
        for (int ch = 0; ch < 8; ch++) {
            int idx = tid + ch * 256;
            int n  = idx >> 4;
            int m8 = (idx & 15) << 3;
            uint4 v = *reinterpret_cast<uint4*>(T + n * 136 + m8);
            *reinterpret_cast<uint4*>(C + (size_t)(nBase + n) * ldc + mBase + m8) = v;
        }
    }
}

// ===========================================================================
// Single fused fp32 -> fp16 convert over all 5 tensors
// ===========================================================================
#define NQ4 (TOK * DIM / 4)   // 1048576
#define NW4 (DIM * DIM / 4)   // 262144
#define NCVT (2 * NQ4 + 3 * NW4)

__global__ __launch_bounds__(256) void tohalf_all(
    const float* __restrict__ q,  const float* __restrict__ k,
    const float* __restrict__ wq, const float* __restrict__ wk,
    const float* __restrict__ wv,
    __half* q16, __half* k16, __half* wq16, __half* wk16, __half* wv16)
{
    int i = blockIdx.x * 256 + threadIdx.x;
    if (i >= NCVT) return;
    const float* src; __half* dst; int j;
    if (i < NQ4)                    { src = q;  dst = q16;  j = i; }
    else if (i < 2 * NQ4)           { src = k;  dst = k16;  j = i - NQ4; }
    else if (i < 2 * NQ4 + NW4)     { src = wq; dst = wq16; j = i - 2 * NQ4; }
    else if (i < 2 * NQ4 + 2 * NW4) { src = wk; dst = wk16; j = i - 2 * NQ4 - NW4; }
    else                            { src = wv; dst = wv16; j = i - 2 * NQ4 - 2 * NW4; }
    float4 v = reinterpret_cast<const float4*>(src)[j];
    uint2 u;
    u.x = packh2(v.x, v.y);
    u.y = packh2(v.z, v.w);
    reinterpret_cast<uint2*>(dst)[j] = u;
}

// ===========================================================================
// Fused flash attention, fp16; S in fp16-acc MMA, PV in fp32-acc.
// grid (16 q-tiles, 16 bh); block 256 (8 warps, warp = 16 q-rows).
// Stage (32KB): K@0 (64tok x 128d folded), Vt@16384 (128d x 64tok). 2 stages.
// ===========================================================================
#define FA_STAGE 32768
#define FA_SMEM  (2 * FA_STAGE)

__device__ __forceinline__ void fa_load_kv(const __half* __restrict__ K,
                                           const __half* __restrict__ Vt,
                                           int tok0, int hd0, int btok,
                                           uint32_t st, int tid) {
#pragma unroll
    for (int i = 0; i < 4; i++) {
        int u = tid + i * 256;
        int t = u >> 4, c = u & 15;
        uint32_t off = SWZ128((((t + ((c >> 3) << 6)) << 7) | ((c & 7) << 4)));
        const __half* g = K + (size_t)(btok + tok0 + t) * DIM + hd0 + (c << 3);
        CP_ASYNC16(st + off, g);
    }
#pragma unroll
    for (int i = 0; i < 4; i++) {
        int u = tid + i * 256;
        int d = u >> 3, c = u & 7;
        uint32_t off = SWZ128(((d << 7) | (c << 4)));
        const __half* g = Vt + (size_t)(hd0 + d) * TOK + btok + tok0 + (c << 3);
        CP_ASYNC16(st + 16384 + off, g);
    }
}

__global__ __launch_bounds__(256, 1) void attn_fused(
    const __half* __restrict__ Q, const __half* __restrict__ K,
    const __half* __restrict__ Vt, float* __restrict__ out)
{
    extern __shared__ char smem[];
    const uint32_t sb = smem_u32(smem);
    const int tid  = threadIdx.x;
    const int wid  = tid >> 5;
    const int lane = tid & 31;
    const int z = blockIdx.y, b = z >> 3, h = z & 7;
    const int bq0  = b * TSEQ + blockIdx.x * 128;
    const int hd0  = h * 128;
    const int btok = b * TSEQ;

    // ---- prologue: Q (128x128) into stage0, folded 256-row layout ----
#pragma unroll
    for (int i = 0; i < 8; i++) {
        int u = tid + i * 256;
        int t = u >> 4, c = u & 15;
        uint32_t off = SWZ128((((t + ((c >> 3) << 7)) << 7) | ((c & 7) << 4)));
        const __half* g = Q + (size_t)(bq0 + t) * DIM + hd0 + (c << 3);
        CP_ASYNC16(sb + off, g);
    }
    CP_COMMIT();
    fa_load_kv(K, Vt, 0, hd0, btok, sb + FA_STAGE, tid);
    CP_COMMIT();
    CP_WAIT1();
    __syncthreads();

    uint32_t qf[8][4];
#pragma unroll
    for (int kc = 0; kc < 8; kc++) {
        int row = wid * 16 + (lane & 7) + ((lane >> 3) & 1) * 8 + ((kc >> 2) << 7);
        int kb  = ((kc & 3) << 5) + ((lane >> 4) << 4);
        uint32_t off = SWZ128((row << 7) | kb);
        LDSM4(qf[kc][0], qf[kc][1], qf[kc][2], qf[kc][3], sb + off);
    }
    __syncthreads();
    fa_load_kv(K, Vt, 64, hd0, btok, sb, tid);   // tile 1 -> stage0
    CP_COMMIT();

    float o[16][4];
#pragma unroll
    for (int i = 0; i < 16; i++)
#pragma unroll
        for (int q = 0; q < 4; q++) o[i][q] = 0.0f;
    float m0 = -INFINITY, m1 = -INFINITY, l0 = 0.0f, l1 = 0.0f;

    for (int it = 0; it < 32; it++) {
        const uint32_t st = sb + (1 - (it & 1)) * FA_STAGE;
        if (it < 31) { CP_WAIT1(); } else { CP_WAIT0(); }
        __syncthreads();

        // ---- S = Q K^T (fp16 accumulate) ----
        uint32_t s16[8][2];
#pragma unroll
        for (int i = 0; i < 8; i++) { s16[i][0] = 0u; s16[i][1] = 0u; }

#pragma unroll
        for (int kc = 0; kc < 8; kc++) {
            const int half = (kc >> 2) << 6;
            const int kb   = ((kc & 3) << 5) + (((lane >> 3) & 1) << 4);
#pragma unroll
            for (int nn = 0; nn < 4; nn++) {
                int row = nn * 16 + (lane & 7) + ((lane >> 4) << 3) + half;
                uint32_t off = SWZ128((row << 7) | kb);
                uint32_t b0, b1, b2, b3;
                LDSM4(b0, b1, b2, b3, st + off);
                MMA16816H(s16[nn * 2],     qf[kc], b0, b1);
                MMA16816H(s16[nn * 2 + 1], qf[kc], b2, b3);
            }
        }

        // unpack fp16 S -> fp32
        float s[8][4];
#pragma unroll
        for (int nf = 0; nf < 8; nf++) {
            float2 f0 = __half22float2(*reinterpret_cast<__half2*>(&s16[nf][0]));
            float2 f1 = __half22float2(*reinterpret_cast<__half2*>(&s16[nf][1]));
            s[nf][0] = f0.x; s[nf][1] = f0.y;
            s[nf][2] = f1.x; s[nf][3] = f1.y;
        }

        // ---- online softmax (rows r=lane>>2 and r+8) ----
        float rmax0 = -INFINITY, rmax1 = -INFINITY;
#pragma unroll
        for (int nf = 0; nf < 8; nf++) {
            rmax0 = fmaxf(rmax0, fmaxf(s[nf][0], s[nf][1]));
            rmax1 = fmaxf(rmax1, fmaxf(s[nf][2], s[nf][3]));
        }
        rmax0 = fmaxf(rmax0, __shfl_xor_sync(0xffffffffu, rmax0, 1));
        rmax0 = fmaxf(rmax0, __shfl_xor_sync(0xffffffffu, rmax0, 2));
        rmax1 = fmaxf(rmax1, __shfl_xor_sync(0xffffffffu, rmax1, 1));
        rmax1 = fmaxf(rmax1, __shfl_xor_sync(0xffffffffu, rmax1, 2));
        const float mn0 = fmaxf(m0, rmax0), mn1 = fmaxf(m1, rmax1);
        const float a0 = __expf(m0 - mn0), a1 = __expf(m1 - mn1);
        float rs0 = 0.0f, rs1 = 0.0f;
#pragma unroll
        for (int nf = 0; nf < 8; nf++) {
            s[nf][0] = __expf(s[nf][0] - mn0);
            s[nf][1] = __expf(s[nf][1] - mn0);
            s[nf][2] = __expf(s[nf][2] - mn1);
            s[nf][3] = __expf(s[nf][3] - mn1);
            rs0 += s[nf][0] + s[nf][1];
            rs1 += s[nf][2] + s[nf][3];
        }
        rs0 += __shfl_xor_sync(0xffffffffu, rs0, 1);
        rs0 += __shfl_xor_sync(0xffffffffu, rs0, 2);
        rs1 += __shfl_xor_sync(0xffffffffu, rs1, 1);
        rs1 += __shfl_xor_sync(0xffffffffu, rs1, 2);
        l0 = l0 * a0 + rs0; l1 = l1 * a1 + rs1;
        m0 = mn0; m1 = mn1;
#pragma unroll
        for (int df = 0; df < 16; df++) {
            o[df][0] *= a0; o[df][1] *= a0;
            o[df][2] *= a1; o[df][3] *= a1;
        }

        // ---- P -> fp16 A-fragments ----
        uint32_t p[4][4];
#pragma unroll
        for (int kv = 0; kv < 4; kv++) {
            p[kv][0] = packh2(s[kv * 2][0],     s[kv * 2][1]);
            p[kv][1] = packh2(s[kv * 2][2],     s[kv * 2][3]);
            p[kv][2] = packh2(s[kv * 2 + 1][0], s[kv * 2 + 1][1]);
            p[kv][3] = packh2(s[kv * 2 + 1][2], s[kv * 2 + 1][3]);
        }

        // ---- O += P V (fp32 accumulate) ----
#pragma unroll
        for (int kv = 0; kv < 4; kv++) {
            const int kb = (kv << 5) + (((lane >> 3) & 1) << 4);
#pragma unroll
            for (int ddf = 0; ddf < 8; ddf++) {
                int row = ddf * 16 + (lane & 7) + ((lane >> 4) << 3);
                uint32_t off = SWZ128((row << 7) | kb);
                uint32_t v0, v1, v2, v3;
                LDSM4(v0, v1, v2, v3, st + 16384 + off);
                MMA16816(o[ddf * 2],     p[kv], v0, v1);
                MMA16816(o[ddf * 2 + 1], p[kv], v2, v3);
            }
        }

        __syncthreads();
        if (it + 2 < 32) {
            fa_load_kv(K, Vt, (it + 2) * 64, hd0, btok, st, tid);
            CP_COMMIT();
        }
    }

    // ---- epilogue: normalize & store ----
    const float inv0 = 1.0f / l0, inv1 = 1.0f / l1;
    const int r0 = wid * 16 + (lane >> 2);
#pragma unroll
    for (int df = 0; df < 16; df++) {
        const int d = hd0 + df * 8 + 2 * (lane & 3);
        float* p0 = out + (size_t)(bq0 + r0) * DIM + d;
        float* p1 = out + (size_t)(bq0 + r0 + 8) * DIM + d;
        *reinterpret_cast<float2*>(p0) = make_float2(o[df][0] * inv0, o[df][1] * inv0);
        *reinterpret_cast<float2*>(p1) = make_float2(o[df][2] * inv1, o[df][3] * inv1);
    }
}

// ===========================================================================
// Launch
// ===========================================================================
extern "C" void kernel_launch(void* const* d_in, const int* in_sizes, int n_in,
                              void* d_out, int out_size)
{
    const float* query = (const float*)d_in[0];
    const float* keys  = (const float*)d_in[1];
    const float* Wq    = (const float*)d_in[2];
    const float* Wk    = (const float*)d_in[3];
    const float* Wv    = (const float*)d_in[4];
    float* out = (float*)d_out;

    __half *q16, *k16, *Wq16, *Wk16, *Wv16, *Q16, *K16, *Vt16;
    cudaGetSymbolAddress((void**)&q16, g_q16);
    cudaGetSymbolAddress((void**)&k16, g_k16);
    cudaGetSymbolAddress((void**)&Wq16, g_Wq16);
    cudaGetSymbolAddress((void**)&Wk16, g_Wk16);
    cudaGetSymbolAddress((void**)&Wv16, g_Wv16);
    cudaGetSymbolAddress((void**)&Q16, g_Q16);
    cudaGetSymbolAddress((void**)&K16, g_K16);
    cudaGetSymbolAddress((void**)&Vt16, g_Vt16);

    cudaFuncSetAttribute(gemm_proj, cudaFuncAttributeMaxDynamicSharedMemorySize,
                         G_SMEM_TOTAL);
    cudaFuncSetAttribute(attn_fused, cudaFuncAttributeMaxDynamicSharedMemorySize,
                         FA_SMEM);

    // 1) convert all inputs to fp16 in one launch
    tohalf_all<<<(NCVT + 255) / 256, 256>>>(query, keys, Wq, Wk, Wv,
                                            q16, k16, Wq16, Wk16, Wv16);

    // 2) projections (Q prescaled by 2^-5; V stored transposed)
    dim3 gp(DIM / 128, TOK / 128);
    gemm_proj<<<gp, 256, G_SMEM_TOTAL>>>(q16, Wq16, Q16, DIM, 1, QSCALE);
    gemm_proj<<<gp, 256, G_SMEM_TOTAL>>>(k16, Wk16, K16, DIM, 1, 1.0f);
    gemm_proj<<<gp, 256, G_SMEM_TOTAL>>>(k16, Wv16, Vt16, TOK, 2, 1.0f);

    // 3) fused flash attention -> out
    dim3 ga(TSEQ / 128, NBH);
    attn_fused<<<ga, 256, FA_SMEM>>>(Q16, K16, Vt16, out);
}

// round 7
// speedup vs baseline: 10.7781x; 1.0513x over previous
#include <cuda_runtime.h>
#include <cuda_fp16.h>
#include <stdint.h>

// ===========================================================================
// Problem constants
// ===========================================================================
#define TOK   4096      // 2*2048 tokens
#define DIM   1024
#define TSEQ  2048
#define NBH   16
#define QSCALE 0.03125f // 1/sqrt(1024) = 2^-5

// ===========================================================================
// Device scratch (allocation-free)
// ===========================================================================
__device__ __align__(16) __half g_q16[TOK * DIM];
__device__ __align__(16) __half g_k16[TOK * DIM];
__device__ __align__(16) __half g_W16[3 * DIM * DIM];   // stacked Wq|Wk|Wv
__device__ __align__(16) __half g_Q16[TOK * DIM];       // Q proj (prescaled 2^-5)
__device__ __align__(16) __half g_K16[TOK * DIM];       // K proj
__device__ __align__(16) __half g_Vt16[DIM * TOK];      // V^T proj

// ===========================================================================
// Helpers
// ===========================================================================
__device__ __forceinline__ uint32_t smem_u32(const void* p) {
    uint32_t a;
    asm("{ .reg .u64 t; cvta.to.shared.u64 t, %1; cvt.u32.u64 %0, t; }" : "=r"(a) : "l"(p));
    return a;
}
#define SWZ128(off) ((off) ^ (((off) >> 3) & 0x70))

#define LDSM4(r0, r1, r2, r3, addr) \
    asm volatile("ldmatrix.sync.aligned.m8n8.x4.shared.b16 {%0,%1,%2,%3}, [%4];" \
                 : "=r"(r0), "=r"(r1), "=r"(r2), "=r"(r3) : "r"(addr))

#define MMA16816(d, a, b0, b1) \
    asm volatile("mma.sync.aligned.m16n8k16.row.col.f32.f16.f16.f32 " \
                 "{%0,%1,%2,%3}, {%4,%5,%6,%7}, {%8,%9}, {%0,%1,%2,%3};" \
                 : "+f"((d)[0]), "+f"((d)[1]), "+f"((d)[2]), "+f"((d)[3]) \
                 : "r"((a)[0]), "r"((a)[1]), "r"((a)[2]), "r"((a)[3]), \
                   "r"(b0), "r"(b1))

#define MMA16816H(d, a, b0, b1) \
    asm volatile("mma.sync.aligned.m16n8k16.row.col.f16.f16.f16.f16 " \
                 "{%0,%1}, {%2,%3,%4,%5}, {%6,%7}, {%0,%1};" \
                 : "+r"((d)[0]), "+r"((d)[1]) \
                 : "r"((a)[0]), "r"((a)[1]), "r"((a)[2]), "r"((a)[3]), \
                   "r"(b0), "r"(b1))

#define CP_ASYNC16(dst, src) \
    asm volatile("cp.async.cg.shared.global [%0], [%1], 16;" :: "r"(dst), "l"(src))
#define CP_COMMIT()  asm volatile("cp.async.commit_group;" ::: "memory")
#define CP_WAIT0()   asm volatile("cp.async.wait_group 0;" ::: "memory")
#define CP_WAIT1()   asm volatile("cp.async.wait_group 1;" ::: "memory")
#define CP_WAIT2()   asm volatile("cp.async.wait_group 2;" ::: "memory")

__device__ __forceinline__ uint32_t packh2(float a, float b) {
    __half2 h = __floats2half2_rn(a, b);
    return *reinterpret_cast<uint32_t*>(&h);
}

// ===========================================================================
// Merged QKV projection GEMM.
// C[m,n] = sum_k A[m,k] * W[nGlob,k], W stacked [3072, 1024].
// grid (3072/128=24, 4096/128=32); block 128 (4 warps, warp tile 64x64).
// 3-stage cp.async, 1 syncthreads per chunk. 2 CTAs/SM.
// pid = nGlob>>10: 0 -> Q16 (scaled), 1 -> K16, 2 -> Vt16 (transposed).
// ===========================================================================
#define P_STAGE 32768
#define P_SMEM  (3 * P_STAGE)   // 96KB

__device__ __forceinline__ void cpa_tile128(const __half* __restrict__ src,
                                            int rowBase, int kt,
                                            uint32_t dstBase, int tid) {
#pragma unroll
    for (int i = 0; i < 8; i++) {
        int u = tid + i * 128;          // 0..1023
        int r = u >> 3;                 // row 0..127
        int cb = (u & 7) << 4;          // byte col 0..112
        uint32_t dst = dstBase + SWZ128((r << 7) | cb);
        const void* gsrc = src + (size_t)(rowBase + r) * DIM + kt + ((u & 7) << 3);
        CP_ASYNC16(dst, gsrc);
    }
}

__global__ __launch_bounds__(128, 2) void gemm_qkv(
    const __half* __restrict__ q16, const __half* __restrict__ k16,
    const __half* __restrict__ W16,
    __half* __restrict__ Q16, __half* __restrict__ K16, __half* __restrict__ Vt16)
{
    extern __shared__ char smem[];
    const uint32_t sb = smem_u32(smem);
    const int tid  = threadIdx.x;
    const int wid  = tid >> 5;
    const int lane = tid & 31;
    const int wm   = wid & 1;          // 2 warps along M (64 rows each)
    const int wn   = wid >> 1;         // 2 warps along N (64 cols each)
    const int nGlob = blockIdx.x * 128;
    const int pid   = nGlob >> 10;     // 0=Q, 1=K, 2=V
    const int nLoc  = nGlob & 1023;
    const int mBase = blockIdx.y * 128;

    const __half* A = (pid == 0) ? q16 : k16;
    const __half* B = W16 + (size_t)pid * DIM * DIM + (size_t)nLoc * DIM;

    const int nc = DIM >> 6;   // 16 chunks

    // prologue: chunks 0,1 -> stages 0,1
    cpa_tile128(A, mBase, 0, sb,             tid);
    cpa_tile128(B, 0,     0, sb + 16384,     tid);
    CP_COMMIT();
    cpa_tile128(A, mBase, 64, sb + P_STAGE,         tid);
    cpa_tile128(B, 0,     64, sb + P_STAGE + 16384, tid);
    CP_COMMIT();

    float acc[4][8][4];
#pragma unroll
    for (int i = 0; i < 4; i++)
#pragma unroll
        for (int j = 0; j < 8; j++)
#pragma unroll
            for (int q = 0; q < 4; q++) acc[i][j][q] = 0.0f;

    const int arow = wm * 64 + ((lane >> 3) & 1) * 8 + (lane & 7);
    const int akb  = (lane >> 4) << 4;
    const int brow = wn * 64 + ((lane >> 4) << 3) + (lane & 7);
    const int bkb  = ((lane >> 3) & 1) << 4;

    int s = 0;          // stage of current chunk
    int sn = 2;         // stage for chunk c+2
    for (int c = 0; c < nc; c++) {
        if (c + 2 < nc) { CP_WAIT1(); } else { CP_WAIT0(); }
        __syncthreads();
        if (c + 2 < nc) {
            const int kt = (c + 2) << 6;
            cpa_tile128(A, mBase, kt, sb + sn * P_STAGE,         tid);
            cpa_tile128(B, 0,     kt, sb + sn * P_STAGE + 16384, tid);
            CP_COMMIT();
        }

        const uint32_t Ab = sb + s * P_STAGE;
        const uint32_t Bb = Ab + 16384;

#pragma unroll
        for (int kk = 0; kk < 4; kk++) {
            const int kb = kk * 32;
            uint32_t af[4][4];
#pragma unroll
            for (int mi = 0; mi < 4; mi++) {
                const int r = arow + mi * 16;
                const uint32_t off = SWZ128((r << 7) | (kb + akb));
                LDSM4(af[mi][0], af[mi][1], af[mi][2], af[mi][3], Ab + off);
            }
#pragma unroll
            for (int nn = 0; nn < 4; nn++) {
                const int n = brow + nn * 16;
                const uint32_t off = SWZ128((n << 7) | (kb + bkb));
                uint32_t b0, b1, b2, b3;
                LDSM4(b0, b1, b2, b3, Bb + off);
#pragma unroll
                for (int mi = 0; mi < 4; mi++) {
                    MMA16816(acc[mi][nn * 2],     af[mi], b0, b1);
                    MMA16816(acc[mi][nn * 2 + 1], af[mi], b2, b3);
                }
            }
        }
        s  = (s  == 2) ? 0 : s + 1;
        sn = (sn == 2) ? 0 : sn + 1;
    }

    if (pid < 2) {
        __half* C = (pid == 0) ? Q16 : K16;
        const float cscale = (pid == 0) ? QSCALE : 1.0f;
        const int erow = mBase + wm * 64 + (lane >> 2);
        const int ecol = nLoc + wn * 64 + 2 * (lane & 3);
#pragma unroll
        for (int mi = 0; mi < 4; mi++)
#pragma unroll
            for (int ni = 0; ni < 8; ni++) {
                const float* a = acc[mi][ni];
#pragma unroll
                for (int half = 0; half < 2; half++) {
                    uint32_t hp = packh2(a[half * 2] * cscale, a[half * 2 + 1] * cscale);
                    size_t o = (size_t)(erow + mi * 16 + half * 8) * DIM + ecol + ni * 8;
                    *reinterpret_cast<uint32_t*>(C + o) = hp;
                }
            }
    } else {
        // transposed store via smem: T[n][m], stride 136 halves (reuses stages)
        __syncthreads();   // all warps done reading stage smem
        __half* T = reinterpret_cast<__half*>(smem);
        const int lrow = wm * 64 + (lane >> 2);
        const int lcol = wn * 64 + 2 * (lane & 3);
#pragma unroll
        for (int mi = 0; mi < 4; mi++)
#pragma unroll
            for (int ni = 0; ni < 8; ni++) {
                const float* a = acc[mi][ni];
#pragma unroll
                for (int q = 0; q < 4; q++) {
                    int row = lrow + mi * 16 + (q >> 1) * 8;
                    int col = lcol + ni * 8 + (q & 1);
                    T[col * 136 + row] = __float2half_rn(a[q]);
                }
            }
        __syncthreads();
#pragma unroll
        for (int ch = 0; ch < 16; ch++) {
            int idx = tid + ch * 128;   // 0..2047
            int n  = idx >> 4;
            int m8 = (idx & 15) << 3;
            uint4 v = *reinterpret_cast<uint4*>(T + n * 136 + m8);
            *reinterpret_cast<uint4*>(Vt16 + (size_t)(nLoc + n) * TOK + mBase + m8) = v;
        }
    }
}

// ===========================================================================
// Single fused fp32 -> fp16 convert over all 5 tensors (W stacked)
// ===========================================================================
#define NQ4 (TOK * DIM / 4)   // 1048576
#define NW4 (DIM * DIM / 4)   // 262144
#define NCVT (2 * NQ4 + 3 * NW4)

__global__ __launch_bounds__(256) void tohalf_all(
    const float* __restrict__ q,  const float* __restrict__ k,
    const float* __restrict__ wq, const float* __restrict__ wk,
    const float* __restrict__ wv,
    __half* q16, __half* k16, __half* w16)
{
    int i = blockIdx.x * 256 + threadIdx.x;
    if (i >= NCVT) return;
    const float* src; __half* dst; int j;
    if (i < NQ4)                    { src = q;  dst = q16;           j = i; }
    else if (i < 2 * NQ4)           { src = k;  dst = k16;           j = i - NQ4; }
    else if (i < 2 * NQ4 + NW4)     { src = wq; dst = w16;           j = i - 2 * NQ4; }
    else if (i < 2 * NQ4 + 2 * NW4) { src = wk; dst = w16 + DIM*DIM; j = i - 2 * NQ4 - NW4; }
    else                            { src = wv; dst = w16 + 2*DIM*DIM; j = i - 2 * NQ4 - 2 * NW4; }
    float4 v = reinterpret_cast<const float4*>(src)[j];
    uint2 u;
    u.x = packh2(v.x, v.y);
    u.y = packh2(v.z, v.w);
    reinterpret_cast<uint2*>(dst)[j] = u;
}

// ===========================================================================
// Fused flash attention, fp16; S fp16-acc, PV fp32-acc.
// grid (16 q-tiles, 16 bh); block 256 (8 warps, warp = 16 q-rows).
// 3 stages x 32KB (K@0 folded 128x128B, Vt@16384), 1 sync per iteration.
// Q prologue staged in stage2 (reused for KV chunk 2 after frag read).
// ===========================================================================
#define FA_STAGE 32768
#define FA_SMEM  (3 * FA_STAGE)   // 96KB

__device__ __forceinline__ void fa_load_kv(const __half* __restrict__ K,
                                           const __half* __restrict__ Vt,
                                           int tok0, int hd0, int btok,
                                           uint32_t st, int tid) {
#pragma unroll
    for (int i = 0; i < 4; i++) {
        int u = tid + i * 256;
        int t = u >> 4, c = u & 15;
        uint32_t off = SWZ128((((t + ((c >> 3) << 6)) << 7) | ((c & 7) << 4)));
        const __half* g = K + (size_t)(btok + tok0 + t) * DIM + hd0 + (c << 3);
        CP_ASYNC16(st + off, g);
    }
#pragma unroll
    for (int i = 0; i < 4; i++) {
        int u = tid + i * 256;
        int d = u >> 3, c = u & 7;
        uint32_t off = SWZ128(((d << 7) | (c << 4)));
        const __half* g = Vt + (size_t)(hd0 + d) * TOK + btok + tok0 + (c << 3);
        CP_ASYNC16(st + 16384 + off, g);
    }
}

__global__ __launch_bounds__(256, 1) void attn_fused(
    const __half* __restrict__ Q, const __half* __restrict__ K,
    const __half* __restrict__ Vt, float* __restrict__ out)
{
    extern __shared__ char smem[];
    const uint32_t sb = smem_u32(smem);
    const int tid  = threadIdx.x;
    const int wid  = tid >> 5;
    const int lane = tid & 31;
    const int z = blockIdx.y, b = z >> 3, h = z & 7;
    const int bq0  = b * TSEQ + blockIdx.x * 128;
    const int hd0  = h * 128;
    const int btok = b * TSEQ;

    // ---- prologue: Q (128x128) -> stage2 (folded 256-row layout) ----
    const uint32_t qst = sb + 2 * FA_STAGE;
#pragma unroll
    for (int i = 0; i < 8; i++) {
        int u = tid + i * 256;
        int t = u >> 4, c = u & 15;
        uint32_t off = SWZ128((((t + ((c >> 3) << 7)) << 7) | ((c & 7) << 4)));
        const __half* g = Q + (size_t)(bq0 + t) * DIM + hd0 + (c << 3);
        CP_ASYNC16(qst + off, g);
    }
    CP_COMMIT();                                    // gQ
    fa_load_kv(K, Vt, 0,  hd0, btok, sb,            tid); CP_COMMIT();  // g0
    fa_load_kv(K, Vt, 64, hd0, btok, sb + FA_STAGE, tid); CP_COMMIT();  // g1
    CP_WAIT2();                                     // Q done
    __syncthreads();

    uint32_t qf[8][4];
#pragma unroll
    for (int kc = 0; kc < 8; kc++) {
        int row = wid * 16 + (lane & 7) + ((lane >> 3) & 1) * 8 + ((kc >> 2) << 7);
        int kb  = ((kc & 3) << 5) + ((lane >> 4) << 4);
        uint32_t off = SWZ128((row << 7) | kb);
        LDSM4(qf[kc][0], qf[kc][1], qf[kc][2], qf[kc][3], qst + off);
    }
    // iter0's top sync orders these Q reads before chunk2 overwrites stage2.

    float o[16][4];
#pragma unroll
    for (int i = 0; i < 16; i++)
#pragma unroll
        for (int q = 0; q < 4; q++) o[i][q] = 0.0f;
    float m0 = -INFINITY, m1 = -INFINITY, l0 = 0.0f, l1 = 0.0f;

    int s = 0, sn = 2;      // current stage, prefetch stage (chunk it+2)
    for (int it = 0; it < 32; it++) {
        const uint32_t st = sb + s * FA_STAGE;
        if (it + 2 < 32) { CP_WAIT1(); } else { CP_WAIT0(); }
        __syncthreads();
        if (it + 2 < 32) {
            fa_load_kv(K, Vt, (it + 2) * 64, hd0, btok, sb + sn * FA_STAGE, tid);
            CP_COMMIT();
        }

        // ---- S = Q K^T (fp16 accumulate) ----
        uint32_t s16[8][2];
#pragma unroll
        for (int i = 0; i < 8; i++) { s16[i][0] = 0u; s16[i][1] = 0u; }

#pragma unroll
        for (int kc = 0; kc < 8; kc++) {
            const int half = (kc >> 2) << 6;
            const int kb   = ((kc & 3) << 5) + (((lane >> 3) & 1) << 4);
#pragma unroll
            for (int nn = 0; nn < 4; nn++) {
                int row = nn * 16 + (lane & 7) + ((lane >> 4) << 3) + half;
                uint32_t off = SWZ128((row << 7) | kb);
                uint32_t b0, b1, b2, b3;
                LDSM4(b0, b1, b2, b3, st + off);
                MMA16816H(s16[nn * 2],     qf[kc], b0, b1);
                MMA16816H(s16[nn * 2 + 1], qf[kc], b2, b3);
            }
        }

        float sv[8][4];
#pragma unroll
        for (int nf = 0; nf < 8; nf++) {
            float2 f0 = __half22float2(*reinterpret_cast<__half2*>(&s16[nf][0]));
            float2 f1 = __half22float2(*reinterpret_cast<__half2*>(&s16[nf][1]));
            sv[nf][0] = f0.x; sv[nf][1] = f0.y;
            sv[nf][2] = f1.x; sv[nf][3] = f1.y;
        }

        // ---- online softmax ----
        float rmax0 = -INFINITY, rmax1 = -INFINITY;
#pragma unroll
        for (int nf = 0; nf < 8; nf++) {
            rmax0 = fmaxf(rmax0, fmaxf(sv[nf][0], sv[nf][1]));
            rmax1 = fmaxf(rmax1, fmaxf(sv[nf][2], sv[nf][3]));
        }
        rmax0 = fmaxf(rmax0, __shfl_xor_sync(0xffffffffu, rmax0, 1));
        rmax0 = fmaxf(rmax0, __shfl_xor_sync(0xffffffffu, rmax0, 2));
        rmax1 = fmaxf(rmax1, __shfl_xor_sync(0xffffffffu, rmax1, 1));
        rmax1 = fmaxf(rmax1, __shfl_xor_sync(0xffffffffu, rmax1, 2));
        const float mn0 = fmaxf(m0, rmax0), mn1 = fmaxf(m1, rmax1);
        const float a0 = __expf(m0 - mn0), a1 = __expf(m1 - mn1);
        float rs0 = 0.0f, rs1 = 0.0f;
#pragma unroll
        for (int nf = 0; nf < 8; nf++) {
            sv[nf][0] = __expf(sv[nf][0] - mn0);
            sv[nf][1] = __expf(sv[nf][1] - mn0);
            sv[nf][2] = __expf(sv[nf][2] - mn1);
            sv[nf][3] = __expf(sv[nf][3] - mn1);
            rs0 += sv[nf][0] + sv[nf][1];
            rs1 += sv[nf][2] + sv[nf][3];
        }
        rs0 += __shfl_xor_sync(0xffffffffu, rs0, 1);
        rs0 += __shfl_xor_sync(0xffffffffu, rs0, 2);
        rs1 += __shfl_xor_sync(0xffffffffu, rs1, 1);
        rs1 += __shfl_xor_sync(0xffffffffu, rs1, 2);
        l0 = l0 * a0 + rs0; l1 = l1 * a1 + rs1;
        m0 = mn0; m1 = mn1;
#pragma unroll
        for (int df = 0; df < 16; df++) {
            o[df][0] *= a0; o[df][1] *= a0;
            o[df][2] *= a1; o[df][3] *= a1;
        }

        // ---- P -> fp16 A-fragments ----
        uint32_t p[4][4];
#pragma unroll
        for (int kv = 0; kv < 4; kv++) {
            p[kv][0] = packh2(sv[kv * 2][0],     sv[kv * 2][1]);
            p[kv][1] = packh2(sv[kv * 2][2],     sv[kv * 2][3]);
            p[kv][2] = packh2(sv[kv * 2 + 1][0], sv[kv * 2 + 1][1]);
            p[kv][3] = packh2(sv[kv * 2 + 1][2], sv[kv * 2 + 1][3]);
        }

        // ---- O += P V (fp32 accumulate) ----
#pragma unroll
        for (int kv = 0; kv < 4; kv++) {
            const int kb = (kv << 5) + (((lane >> 3) & 1) << 4);
#pragma unroll
            for (int ddf = 0; ddf < 8; ddf++) {
                int row = ddf * 16 + (lane & 7) + ((lane >> 4) << 3);
                uint32_t off = SWZ128((row << 7) | kb);
                uint32_t v0, v1, v2, v3;
                LDSM4(v0, v1, v2, v3, st + 16384 + off);
                MMA16816(o[ddf * 2],     p[kv], v0, v1);
                MMA16816(o[ddf * 2 + 1], p[kv], v2, v3);
            }
        }

        s  = (s  == 2) ? 0 : s + 1;
        sn = (sn == 2) ? 0 : sn + 1;
    }

    // ---- epilogue: normalize & store ----
    const float inv0 = 1.0f / l0, inv1 = 1.0f / l1;
    const int r0 = wid * 16 + (lane >> 2);
#pragma unroll
    for (int df = 0; df < 16; df++) {
        const int d = hd0 + df * 8 + 2 * (lane & 3);
        float* p0 = out + (size_t)(bq0 + r0) * DIM + d;
        float* p1 = out + (size_t)(bq0 + r0 + 8) * DIM + d;
        *reinterpret_cast<float2*>(p0) = make_float2(o[df][0] * inv0, o[df][1] * inv0);
        *reinterpret_cast<float2*>(p1) = make_float2(o[df][2] * inv1, o[df][3] * inv1);
    }
}

// ===========================================================================
// Launch
// ===========================================================================
extern "C" void kernel_launch(void* const* d_in, const int* in_sizes, int n_in,
                              void* d_out, int out_size)
{
    const float* query = (const float*)d_in[0];
    const float* keys  = (const float*)d_in[1];
    const float* Wq    = (const float*)d_in[2];
    const float* Wk    = (const float*)d_in[3];
    const float* Wv    = (const float*)d_in[4];
    float* out = (float*)d_out;

    __half *q16, *k16, *W16, *Q16, *K16, *Vt16;
    cudaGetSymbolAddress((void**)&q16, g_q16);
    cudaGetSymbolAddress((void**)&k16, g_k16);
    cudaGetSymbolAddress((void**)&W16, g_W16);
    cudaGetSymbolAddress((void**)&Q16, g_Q16);
    cudaGetSymbolAddress((void**)&K16, g_K16);
    cudaGetSymbolAddress((void**)&Vt16, g_Vt16);

    cudaFuncSetAttribute(gemm_qkv, cudaFuncAttributeMaxDynamicSharedMemorySize,
                         P_SMEM);
    cudaFuncSetAttribute(attn_fused, cudaFuncAttributeMaxDynamicSharedMemorySize,
                         FA_SMEM);

    // 1) convert all inputs to fp16 (W stacked) in one launch
    tohalf_all<<<(NCVT + 255) / 256, 256>>>(query, keys, Wq, Wk, Wv, q16, k16, W16);

    // 2) merged QKV projections
    dim3 gp(3 * DIM / 128, TOK / 128);   // (24, 32)
    gemm_qkv<<<gp, 128, P_SMEM>>>(q16, k16, W16, Q16, K16, Vt16);

    // 3) fused flash attention -> out
    dim3 ga(TSEQ / 128, NBH);
    attn_fused<<<ga, 256, FA_SMEM>>>(Q16, K16, Vt16, out);
}